// round 1
// baseline (speedup 1.0000x reference)
#include <cuda_runtime.h>
#include <math.h>

// ---------------- problem dims ----------------
#define BATCH   8
#define CDIM    256
#define INNER   512
#define NHEADS  8
#define DHEAD   64
#define HQ      96
#define WQ      96
#define NPIX    (HQ*WQ)     // 9216
#define HC      64
#define WC      64
#define CPIX    (HC*WC)     // 4096
#define BH      (BATCH*NHEADS) // 64
#define NKV     64          // 8x8 pruned
#define EPS     1e-5f
#define NQBLK   (NPIX/256)  // 36

// ---------------- scratch (static device memory; no allocs) ----------------
__device__ float g_ctxn[BATCH*CDIM*CPIX];     // normalized context
__device__ float g_qsn [BATCH*CDIM*NPIX];     // normalized query source
__device__ float g_q   [BATCH*INNER*NPIX];    // q projection (b, h*d, px)
__device__ float g_k   [BATCH*INNER*CPIX];    // k projection
__device__ float g_attno[BATCH*INNER*NPIX];   // attention output (b, h*d, px)
__device__ float g_obuf[BATCH*CDIM*NPIX];     // w_out result before final norm
__device__ float g_qinv[BH*NPIX];
__device__ float g_kinv[BH*CPIX];
__device__ float g_probe_part[BH*NQBLK*DHEAD];
__device__ float g_probe[BH*DHEAD];
__device__ float g_rowsum[BH*DHEAD*HC];
__device__ float g_colsum[BH*DHEAD*WC];
__device__ int   g_topidx[BH*NKV];
__device__ float g_kpack[BH*NKV*DHEAD];       // [bh][j][d]
__device__ float g_vpack[BH*NKV*DHEAD];

// ---------------- channel layernorm (axis=1) ----------------
__global__ void channorm_k(const float* __restrict__ x, const float* __restrict__ g,
                           const float* __restrict__ bb, float* __restrict__ y, int HW) {
    int px = blockIdx.x*256 + threadIdx.x;
    int b  = blockIdx.y;
    const float* xb = x + (size_t)b*CDIM*HW + px;
    float s = 0.f, s2 = 0.f;
    #pragma unroll 8
    for (int c = 0; c < CDIM; c++) { float v = xb[(size_t)c*HW]; s += v; s2 += v*v; }
    float mean = s * (1.f/CDIM);
    float var  = s2 * (1.f/CDIM) - mean*mean;
    float rstd = rsqrtf(var + EPS);
    float* yb = y + (size_t)b*CDIM*HW + px;
    #pragma unroll 8
    for (int c = 0; c < CDIM; c++)
        yb[(size_t)c*HW] = (xb[(size_t)c*HW] - mean) * rstd * g[c] + bb[c];
}

// ---------------- generic batched GEMM: C[b] = A (MxK) * B[b] (KxN) ----------------
#define GBM 128
#define GBN 128
#define GBK 16
__global__ void gemm_k(const float* __restrict__ A, const float* __restrict__ Bm,
                       float* __restrict__ C, int M, int N, int K,
                       long strideB, long strideC) {
    __shared__ float As[GBK][GBM];
    __shared__ float Bs[GBK][GBN];
    const float* Bp = Bm + (size_t)blockIdx.z * strideB;
    float*       Cp = C  + (size_t)blockIdx.z * strideC;
    int row0 = blockIdx.y * GBM;
    int col0 = blockIdx.x * GBN;
    int tid = threadIdx.x;
    int tx = tid & 15, ty = tid >> 4;
    float acc[8][8];
    #pragma unroll
    for (int i = 0; i < 8; i++)
        #pragma unroll
        for (int j = 0; j < 8; j++) acc[i][j] = 0.f;

    for (int k0 = 0; k0 < K; k0 += GBK) {
        #pragma unroll
        for (int i = 0; i < 8; i++) {
            int idx = tid + i*256; int r = idx >> 4, c = idx & 15;
            As[c][r] = A[(size_t)(row0 + r)*K + k0 + c];
        }
        #pragma unroll
        for (int i = 0; i < 8; i++) {
            int idx = tid + i*256; int r = idx >> 7, c = idx & 127;
            Bs[r][c] = Bp[(size_t)(k0 + r)*N + col0 + c];
        }
        __syncthreads();
        #pragma unroll
        for (int kk = 0; kk < GBK; kk++) {
            float a[8], bv[8];
            #pragma unroll
            for (int i = 0; i < 8; i++) a[i]  = As[kk][ty*8 + i];
            #pragma unroll
            for (int j = 0; j < 8; j++) bv[j] = Bs[kk][tx*8 + j];
            #pragma unroll
            for (int i = 0; i < 8; i++)
                #pragma unroll
                for (int j = 0; j < 8; j++) acc[i][j] += a[i]*bv[j];
        }
        __syncthreads();
    }
    #pragma unroll
    for (int i = 0; i < 8; i++)
        #pragma unroll
        for (int j = 0; j < 8; j++)
            Cp[(size_t)(row0 + ty*8 + i)*N + col0 + tx*8 + j] = acc[i][j];
}

// ---------------- q scan: per-pixel inv L2 norm + probe partials ----------------
__global__ void qscan_k(const float* __restrict__ q, float* __restrict__ qinv,
                        float* __restrict__ probe_part) {
    int bh = blockIdx.y;
    int px = blockIdx.x*256 + threadIdx.x;
    const float* base = q + (size_t)bh*DHEAD*NPIX + px;
    float s2 = 0.f;
    #pragma unroll 8
    for (int d = 0; d < DHEAD; d++) { float v = base[(size_t)d*NPIX]; s2 += v*v; }
    float inv = 1.f / fmaxf(sqrtf(s2), 1e-12f);
    qinv[(size_t)bh*NPIX + px] = inv;

    __shared__ float red2[DHEAD][8];
    int lane = threadIdx.x & 31, wid = threadIdx.x >> 5;
    for (int d = 0; d < DHEAD; d++) {
        float v = base[(size_t)d*NPIX] * inv;
        #pragma unroll
        for (int off = 16; off; off >>= 1) v += __shfl_xor_sync(0xffffffffu, v, off);
        if (lane == 0) red2[d][wid] = v;
    }
    __syncthreads();
    if (threadIdx.x < DHEAD) {
        float s = 0.f;
        #pragma unroll
        for (int w = 0; w < 8; w++) s += red2[threadIdx.x][w];
        probe_part[((size_t)bh*NQBLK + blockIdx.x)*DHEAD + threadIdx.x] = s;
    }
}

__global__ void probe_reduce_k(const float* __restrict__ part, float* __restrict__ probe) {
    int bh = blockIdx.x, d = threadIdx.x;
    float s = 0.f;
    for (int i = 0; i < NQBLK; i++) s += part[((size_t)bh*NQBLK + i)*DHEAD + d];
    probe[bh*DHEAD + d] = s;
}

// ---------------- k inv norm ----------------
__global__ void kinv_k(const float* __restrict__ k, float* __restrict__ kinv) {
    int bh = blockIdx.y;
    int px = blockIdx.x*256 + threadIdx.x;
    const float* base = k + (size_t)bh*DHEAD*CPIX + px;
    float s2 = 0.f;
    #pragma unroll 8
    for (int d = 0; d < DHEAD; d++) { float v = base[(size_t)d*CPIX]; s2 += v*v; }
    kinv[(size_t)bh*CPIX + px] = 1.f / fmaxf(sqrtf(s2), 1e-12f);
}

// ---------------- row/col |k| sums (block per (d, bh)) ----------------
__global__ void rowcol_k(const float* __restrict__ k, const float* __restrict__ kinv,
                         float* __restrict__ rowsum, float* __restrict__ colsum) {
    int d = blockIdx.x, bh = blockIdx.y, t = threadIdx.x; // 64 threads
    __shared__ float s[64*65];
    const float* base = k + ((size_t)bh*DHEAD + d)*CPIX;
    const float* inv  = kinv + (size_t)bh*CPIX;
    for (int h = 0; h < 64; h++) {
        int px = h*64 + t;
        s[h*65 + t] = fabsf(base[px]) * inv[px];
    }
    __syncthreads();
    float rs = 0.f, cs = 0.f;
    #pragma unroll 8
    for (int w = 0; w < 64; w++) rs += s[t*65 + w];
    #pragma unroll 8
    for (int h = 0; h < 64; h++) cs += s[h*65 + t];
    rowsum[((size_t)bh*DHEAD + d)*HC + t] = rs;
    colsum[((size_t)bh*DHEAD + d)*WC + t] = cs;
}

// ---------------- scores + exact top-8 (first index wins ties, like lax.top_k) ----------------
__global__ void topk_k(const float* __restrict__ probe, const float* __restrict__ rowsum,
                       const float* __restrict__ colsum, int* __restrict__ topidx) {
    int bh = blockIdx.x, t = threadIdx.x; // 64 threads
    __shared__ float sr[64], sc[64];
    __shared__ int th[8], tw[8];
    float r = 0.f, c = 0.f;
    for (int d = 0; d < DHEAD; d++) {
        float p = probe[bh*DHEAD + d];
        r += p * rowsum[((size_t)bh*DHEAD + d)*HC + t];
        c += p * colsum[((size_t)bh*DHEAD + d)*WC + t];
    }
    sr[t] = r; sc[t] = c;
    __syncthreads();
    if (t == 0) {
        bool used[64];
        for (int i = 0; i < 64; i++) used[i] = false;
        for (int i = 0; i < 8; i++) {
            float best = -1e38f; int bi = 0;
            for (int h = 0; h < 64; h++)
                if (!used[h] && sr[h] > best) { best = sr[h]; bi = h; }
            used[bi] = true; th[i] = bi;
        }
        for (int i = 0; i < 64; i++) used[i] = false;
        for (int i = 0; i < 8; i++) {
            float best = -1e38f; int bi = 0;
            for (int w = 0; w < 64; w++)
                if (!used[w] && sc[w] > best) { best = sc[w]; bi = w; }
            used[bi] = true; tw[i] = bi;
        }
        for (int i = 0; i < 8; i++)
            for (int j = 0; j < 8; j++)
                topidx[bh*NKV + i*8 + j] = th[i]*WC + tw[j];
    }
}

// ---------------- pack: gather+normalize k; compute v only at pruned positions ----------------
// dynamic smem: ctx_s[256][64] = 64KB
__global__ void pack_k(const float* __restrict__ k, const float* __restrict__ kinv,
                       const float* __restrict__ ctxn, const float* __restrict__ wkv,
                       const int* __restrict__ topidx,
                       float* __restrict__ kpack, float* __restrict__ vpack) {
    extern __shared__ float ctx_s[];   // [c][j] = ctx_s[c*64 + j]
    __shared__ int pos[NKV];
    int bh = blockIdx.x, b = bh >> 3, h = bh & 7;
    int tid = threadIdx.x;
    if (tid < NKV) pos[tid] = topidx[bh*NKV + tid];
    __syncthreads();

    // stage context columns at pruned positions
    int j = tid & 63, c0 = tid >> 6;
    for (int cc = 0; cc < 64; cc++) {
        int c = cc*4 + c0;
        ctx_s[c*64 + j] = ctxn[((size_t)b*CDIM + c)*CPIX + pos[j]];
    }

    // k gather + normalize
    #pragma unroll
    for (int i = 0; i < 16; i++) {
        int idx = tid + i*256;
        int jj = idx >> 6, d = idx & 63;
        int p = pos[jj];
        kpack[(size_t)bh*NKV*DHEAD + idx] =
            k[((size_t)bh*DHEAD + d)*CPIX + p] * kinv[(size_t)bh*CPIX + p];
    }
    __syncthreads();

    // v = w_v rows (INNER + h*64 + d) applied at pruned columns
    for (int dd = 0; dd < 16; dd++) {
        int d = dd*4 + c0;
        const float* wr = wkv + ((size_t)(INNER + h*DHEAD + d))*CDIM;
        float acc = 0.f;
        #pragma unroll 8
        for (int c = 0; c < CDIM; c++) acc += wr[c] * ctx_s[c*64 + j];
        vpack[(size_t)bh*NKV*DHEAD + j*DHEAD + d] = acc;
    }
}

// ---------------- fused attention: 128-query tile x 64 KV, full softmax in-block ----------------
// dyn smem: Ks[64][65] + Vs[64][65] + Qs[64][129] + P[128][65] = 99584 B
#define ATTN_SMEM ((64*65 + 64*65 + 64*129 + 128*65) * 4)
__global__ void attn_k(const float* __restrict__ q, const float* __restrict__ qinv,
                       const float* __restrict__ kpack, const float* __restrict__ vpack,
                       float* __restrict__ outb) {
    extern __shared__ float sm[];
    float* Ks = sm;                 // [j][d] pad 65
    float* Vs = Ks + 64*65;         // [j][d] pad 65
    float* Qs = Vs + 64*65;         // [d][p] pad 129 (reused as out_s)
    float* P  = Qs + 64*129;        // [p][j] pad 65

    int bh = blockIdx.y;
    int px0 = blockIdx.x * 128;
    int tid = threadIdx.x;
    int tx = tid & 15, ty = tid >> 4;

    for (int i = tid; i < NKV*DHEAD; i += 256) {
        int jj = i >> 6, d = i & 63;
        Ks[jj*65 + d] = kpack[(size_t)bh*NKV*DHEAD + i];
        Vs[jj*65 + d] = vpack[(size_t)bh*NKV*DHEAD + i];
    }
    const float* qb = q + (size_t)bh*DHEAD*NPIX + px0;
    const float* qi = qinv + (size_t)bh*NPIX + px0;
    for (int i = tid; i < 8192; i += 256) {
        int d = i >> 7, p = i & 127;
        Qs[d*129 + p] = qb[(size_t)d*NPIX + p] * qi[p];
    }
    __syncthreads();

    // sim[p][j], per-thread tile 8p x 4j
    float acc[8][4];
    #pragma unroll
    for (int i = 0; i < 8; i++)
        #pragma unroll
        for (int jj = 0; jj < 4; jj++) acc[i][jj] = 0.f;
    for (int d = 0; d < DHEAD; d++) {
        float a[8], bv[4];
        #pragma unroll
        for (int i = 0; i < 8; i++)  a[i]  = Qs[d*129 + ty*8 + i];
        #pragma unroll
        for (int jj = 0; jj < 4; jj++) bv[jj] = Ks[(tx*4 + jj)*65 + d];
        #pragma unroll
        for (int i = 0; i < 8; i++)
            #pragma unroll
            for (int jj = 0; jj < 4; jj++) acc[i][jj] += a[i]*bv[jj];
    }
    #pragma unroll
    for (int i = 0; i < 8; i++)
        #pragma unroll
        for (int jj = 0; jj < 4; jj++)
            P[(ty*8 + i)*65 + tx*4 + jj] = acc[i][jj];
    __syncthreads();

    // softmax per row (64 cols): 8 warps x 16 rows
    int lane = tid & 31, w = tid >> 5;
    for (int r = w; r < 128; r += 8) {
        float m = -1e30f;
        #pragma unroll
        for (int j = lane; j < 64; j += 32) m = fmaxf(m, P[r*65 + j]);
        #pragma unroll
        for (int off = 16; off; off >>= 1) m = fmaxf(m, __shfl_xor_sync(0xffffffffu, m, off));
        float s = 0.f;
        #pragma unroll
        for (int j = lane; j < 64; j += 32) { float e = expf(P[r*65 + j] - m); P[r*65 + j] = e; s += e; }
        #pragma unroll
        for (int off = 16; off; off >>= 1) s += __shfl_xor_sync(0xffffffffu, s, off);
        float invs = 1.f / s;
        #pragma unroll
        for (int j = lane; j < 64; j += 32) P[r*65 + j] *= invs;
    }
    __syncthreads();

    // out[p][d] = P @ V, per-thread tile 8p x 4d
    float acc2[8][4];
    #pragma unroll
    for (int i = 0; i < 8; i++)
        #pragma unroll
        for (int jj = 0; jj < 4; jj++) acc2[i][jj] = 0.f;
    for (int j = 0; j < NKV; j++) {
        float a[8], bv[4];
        #pragma unroll
        for (int i = 0; i < 8; i++)  a[i]  = P[(ty*8 + i)*65 + j];
        #pragma unroll
        for (int jj = 0; jj < 4; jj++) bv[jj] = Vs[j*65 + tx*4 + jj];
        #pragma unroll
        for (int i = 0; i < 8; i++)
            #pragma unroll
            for (int jj = 0; jj < 4; jj++) acc2[i][jj] += a[i]*bv[jj];
    }
    __syncthreads();  // everyone done reading Qs/P before Qs is reused as out_s
    #pragma unroll
    for (int i = 0; i < 8; i++)
        #pragma unroll
        for (int jj = 0; jj < 4; jj++)
            Qs[(tx*4 + jj)*129 + ty*8 + i] = acc2[i][jj];
    __syncthreads();
    float* ob = outb + (size_t)bh*DHEAD*NPIX + px0;
    for (int i = tid; i < 8192; i += 256) {
        int d = i >> 7, p = i & 127;
        ob[(size_t)d*NPIX + p] = Qs[d*129 + p];
    }
}

// ---------------- final: channorm(obuf)*gamma + residual ----------------
__global__ void final_k(const float* __restrict__ x, const float* __restrict__ g,
                        const float* __restrict__ bb, const float* __restrict__ gamma,
                        const float* __restrict__ resid, float* __restrict__ y) {
    int px = blockIdx.x*256 + threadIdx.x;
    int b  = blockIdx.y;
    const float* xb = x + (size_t)b*CDIM*NPIX + px;
    float s = 0.f, s2 = 0.f;
    #pragma unroll 8
    for (int c = 0; c < CDIM; c++) { float v = xb[(size_t)c*NPIX]; s += v; s2 += v*v; }
    float mean = s * (1.f/CDIM);
    float var  = s2 * (1.f/CDIM) - mean*mean;
    float rstd = rsqrtf(var + EPS);
    float gm = gamma[0];
    const float* rb = resid + (size_t)b*CDIM*NPIX + px;
    float* yb = y + (size_t)b*CDIM*NPIX + px;
    #pragma unroll 8
    for (int c = 0; c < CDIM; c++)
        yb[(size_t)c*NPIX] = gm * ((xb[(size_t)c*NPIX] - mean)*rstd*g[c] + bb[c]) + rb[(size_t)c*NPIX];
}

// ---------------- launch ----------------
extern "C" void kernel_launch(void* const* d_in, const int* in_sizes, int n_in,
                              void* d_out, int out_size) {
    const float* query_source = (const float*)d_in[0];
    const float* context      = (const float*)d_in[1];
    const float* qs_g  = (const float*)d_in[2];
    const float* qs_b  = (const float*)d_in[3];
    const float* ctx_g = (const float*)d_in[4];
    const float* ctx_b = (const float*)d_in[5];
    const float* out_g = (const float*)d_in[6];
    const float* out_b = (const float*)d_in[7];
    const float* w_q   = (const float*)d_in[8];
    const float* w_kv  = (const float*)d_in[9];
    const float* w_out = (const float*)d_in[10];
    const float* gamma = (const float*)d_in[11];
    float* out = (float*)d_out;

    float *ctxn, *qsn, *qb, *kb, *attno, *obuf, *qinv, *kinv, *ppart, *probe,
          *rowsum, *colsum, *kpack, *vpack;
    int* topidx;
    cudaGetSymbolAddress((void**)&ctxn,  g_ctxn);
    cudaGetSymbolAddress((void**)&qsn,   g_qsn);
    cudaGetSymbolAddress((void**)&qb,    g_q);
    cudaGetSymbolAddress((void**)&kb,    g_k);
    cudaGetSymbolAddress((void**)&attno, g_attno);
    cudaGetSymbolAddress((void**)&obuf,  g_obuf);
    cudaGetSymbolAddress((void**)&qinv,  g_qinv);
    cudaGetSymbolAddress((void**)&kinv,  g_kinv);
    cudaGetSymbolAddress((void**)&ppart, g_probe_part);
    cudaGetSymbolAddress((void**)&probe, g_probe);
    cudaGetSymbolAddress((void**)&rowsum,g_rowsum);
    cudaGetSymbolAddress((void**)&colsum,g_colsum);
    cudaGetSymbolAddress((void**)&topidx,g_topidx);
    cudaGetSymbolAddress((void**)&kpack, g_kpack);
    cudaGetSymbolAddress((void**)&vpack, g_vpack);

    cudaFuncSetAttribute(attn_k, cudaFuncAttributeMaxDynamicSharedMemorySize, ATTN_SMEM);
    cudaFuncSetAttribute(pack_k, cudaFuncAttributeMaxDynamicSharedMemorySize, 256*64*4);

    // 1) channel layernorms
    channorm_k<<<dim3(CPIX/256, BATCH), 256>>>(context, ctx_g, ctx_b, ctxn, CPIX);
    channorm_k<<<dim3(NPIX/256, BATCH), 256>>>(query_source, qs_g, qs_b, qsn, NPIX);

    // 2) projections (k only; v deferred to pruned positions)
    gemm_k<<<dim3(CPIX/GBN, INNER/GBM, BATCH), 256>>>(
        w_kv, ctxn, kb, INNER, CPIX, CDIM, (long)CDIM*CPIX, (long)INNER*CPIX);
    gemm_k<<<dim3(NPIX/GBN, INNER/GBM, BATCH), 256>>>(
        w_q, qsn, qb, INNER, NPIX, CDIM, (long)CDIM*NPIX, (long)INNER*NPIX);

    // 3) norms + probe + pruning scores
    qscan_k<<<dim3(NQBLK, BH), 256>>>(qb, qinv, ppart);
    probe_reduce_k<<<BH, DHEAD>>>(ppart, probe);
    kinv_k<<<dim3(CPIX/256, BH), 256>>>(kb, kinv);
    rowcol_k<<<dim3(DHEAD, BH), 64>>>(kb, kinv, rowsum, colsum);
    topk_k<<<BH, 64>>>(probe, rowsum, colsum, topidx);

    // 4) pack pruned K, compute pruned V
    pack_k<<<BH, 256, 256*64*4>>>(kb, kinv, ctxn, w_kv, topidx, kpack, vpack);

    // 5) fused attention
    attn_k<<<dim3(NPIX/128, BH), 256, ATTN_SMEM>>>(qb, qinv, kpack, vpack, attno);

    // 6) output projection
    gemm_k<<<dim3(NPIX/GBN, CDIM/GBM, BATCH), 256>>>(
        w_out, attno, obuf, CDIM, NPIX, INNER, (long)INNER*NPIX, (long)CDIM*NPIX);

    // 7) final norm + gamma + residual
    final_k<<<dim3(NPIX/256, BATCH), 256>>>(obuf, out_g, out_b, gamma, query_source, out);
}

// round 3
// speedup vs baseline: 1.6661x; 1.6661x over previous
#include <cuda_runtime.h>
#include <cuda_bf16.h>
#include <math.h>
#include <stdint.h>

// ---------------- problem dims ----------------
#define BATCH   8
#define CDIM    256
#define INNER   512
#define NHEADS  8
#define DHEAD   64
#define HQ      96
#define WQ      96
#define NPIX    (HQ*WQ)     // 9216
#define HC      64
#define WC      64
#define CPIX    (HC*WC)     // 4096
#define BH      (BATCH*NHEADS) // 64
#define NKV     64          // 8x8 pruned
#define EPS     1e-5f
#define NQBLK   (NPIX/256)  // 36

// ---------------- scratch (static device memory; no allocs) ----------------
__device__ float g_ctxn [BATCH*CDIM*CPIX];     // normalized context (fp32, for V)
__device__ float g_q    [BATCH*INNER*NPIX];    // q projection (b, h*d, px)
__device__ float g_k    [BATCH*INNER*CPIX];    // k projection
__device__ float g_obuf [BATCH*CDIM*NPIX];     // w_out result before final norm
__device__ float g_qinv [BH*NPIX];
__device__ float g_kinv [BH*CPIX];
__device__ float g_probe_part[BH*NQBLK*DHEAD];
__device__ float g_probe[BH*DHEAD];
__device__ float g_rowsum[BH*DHEAD*HC];
__device__ float g_colsum[BH*DHEAD*WC];
__device__ int   g_topidx[BH*NKV];
__device__ float g_kpack[BH*NKV*DHEAD];
__device__ float g_vpack[BH*NKV*DHEAD];
// bf16 hi/lo split operands
__device__ __nv_bfloat16 g_ctxn_h[BATCH*CDIM*CPIX], g_ctxn_l[BATCH*CDIM*CPIX];
__device__ __nv_bfloat16 g_qsn_h [BATCH*CDIM*NPIX], g_qsn_l [BATCH*CDIM*NPIX];
__device__ __nv_bfloat16 g_att_h [BATCH*INNER*NPIX], g_att_l [BATCH*INNER*NPIX];
__device__ __nv_bfloat16 g_wq_h  [INNER*CDIM], g_wq_l  [INNER*CDIM];
__device__ __nv_bfloat16 g_wk_h  [INNER*CDIM], g_wk_l  [INNER*CDIM];
__device__ __nv_bfloat16 g_wout_h[CDIM*INNER], g_wout_l[CDIM*INNER];

// ---------------- weight hi/lo split ----------------
__global__ void split_w_k(const float* __restrict__ src, __nv_bfloat16* __restrict__ dh,
                          __nv_bfloat16* __restrict__ dl, int n) {
    for (int i = blockIdx.x*blockDim.x + threadIdx.x; i < n; i += gridDim.x*blockDim.x) {
        float v = src[i];
        __nv_bfloat16 h = __float2bfloat16(v);
        dh[i] = h;
        dl[i] = __float2bfloat16(v - __bfloat162float(h));
    }
}

// ---------------- channel layernorm (axis=1), writes fp32(optional) + bf16 hi/lo ----------------
__global__ void channorm_split_k(const float* __restrict__ x, const float* __restrict__ g,
                                 const float* __restrict__ bb, float* __restrict__ yf,
                                 __nv_bfloat16* __restrict__ yh, __nv_bfloat16* __restrict__ yl,
                                 int HW) {
    int px = blockIdx.x*256 + threadIdx.x;
    int b  = blockIdx.y;
    const float* xb = x + (size_t)b*CDIM*HW + px;
    float s = 0.f, s2 = 0.f;
    #pragma unroll 8
    for (int c = 0; c < CDIM; c++) { float v = xb[(size_t)c*HW]; s += v; s2 += v*v; }
    float mean = s * (1.f/CDIM);
    float var  = s2 * (1.f/CDIM) - mean*mean;
    float rstd = rsqrtf(var + EPS);
    size_t base = (size_t)b*CDIM*HW + px;
    #pragma unroll 8
    for (int c = 0; c < CDIM; c++) {
        float v = (xb[(size_t)c*HW] - mean) * rstd * g[c] + bb[c];
        if (yf) yf[base + (size_t)c*HW] = v;
        __nv_bfloat16 h = __float2bfloat16(v);
        yh[base + (size_t)c*HW] = h;
        yl[base + (size_t)c*HW] = __float2bfloat16(v - __bfloat162float(h));
    }
}

// ---------------- warp-MMA (HMMA bf16) split GEMM ----------------
// C[b](M x N) = W(M x K) @ X[b](K x N), fp32 via 3-term bf16 split.
// CTA: 256 thr = 8 warps (4m x 2n), tile 128(M) x 64(N), K chunk 32.
#define AST 40   // A smem row stride (bf16 elems), 80B — conflict-free frag loads
#define BST 68   // B smem row stride (bf16 elems), 136B

__device__ __forceinline__ void mma_bf16(float* c, const uint32_t* a, const uint32_t* b) {
    asm volatile(
        "mma.sync.aligned.m16n8k16.row.col.f32.bf16.bf16.f32 "
        "{%0,%1,%2,%3}, {%4,%5,%6,%7}, {%8,%9}, {%0,%1,%2,%3};\n"
        : "+f"(c[0]), "+f"(c[1]), "+f"(c[2]), "+f"(c[3])
        : "r"(a[0]), "r"(a[1]), "r"(a[2]), "r"(a[3]), "r"(b[0]), "r"(b[1]));
}

__global__ void __launch_bounds__(256)
hmma_gemm_k(const __nv_bfloat16* __restrict__ Wh, const __nv_bfloat16* __restrict__ Wl,
            const __nv_bfloat16* __restrict__ Xh, const __nv_bfloat16* __restrict__ Xl,
            float* __restrict__ C, int M, int N, int K,
            long strideX, long strideC) {
    __shared__ __nv_bfloat16 As[2][128*AST];  // [term][m][k]
    __shared__ __nv_bfloat16 Bs[2][32*BST];   // [term][k][n]

    int tid = threadIdx.x;
    int wid = tid >> 5, lane = tid & 31;
    int wm = wid & 3, wn = wid >> 2;
    int n0 = blockIdx.x * 64;
    int m0 = blockIdx.y * 128;
    const __nv_bfloat16* Xhp = Xh + (size_t)blockIdx.z * strideX;
    const __nv_bfloat16* Xlp = Xl + (size_t)blockIdx.z * strideX;
    float* Cp = C + (size_t)blockIdx.z * strideC;

    float acc[2][4][4];
    #pragma unroll
    for (int i = 0; i < 2; i++)
        #pragma unroll
        for (int j = 0; j < 4; j++)
            #pragma unroll
            for (int l = 0; l < 4; l++) acc[i][j][l] = 0.f;

    int nch = K >> 5;
    for (int ch = 0; ch < nch; ch++) {
        int k0 = ch << 5;
        // stage A: 2 terms x 128 rows x 4 uint4 segs
        #pragma unroll
        for (int u = 0; u < 4; u++) {
            int idx = tid + u*256;
            int term = idx >> 9, v = idx & 511;
            int row = v >> 2, seg = v & 3;
            const __nv_bfloat16* src = (term ? Wl : Wh) + (size_t)(m0 + row)*K + k0 + seg*8;
            *(uint4*)&As[term][row*AST + seg*8] = *(const uint4*)src;
        }
        // stage B: 2 terms x 32 k x 16 uint2 groups (4 n each)
        #pragma unroll
        for (int u = 0; u < 4; u++) {
            int idx = tid + u*256;
            int term = idx >> 9, v = idx & 511;
            int k = v >> 4, gg = v & 15;
            const __nv_bfloat16* src = (term ? Xlp : Xhp) + (size_t)(k0 + k)*N + n0 + gg*4;
            *(uint2*)&Bs[term][k*BST + gg*4] = *(const uint2*)src;
        }
        __syncthreads();

        #pragma unroll
        for (int kk = 0; kk < 2; kk++) {
            // A fragments
            uint32_t af[2][2][4];
            #pragma unroll
            for (int t = 0; t < 2; t++) {
                const uint32_t* A32 = (const uint32_t*)&As[t][0];
                #pragma unroll
                for (int tm = 0; tm < 2; tm++) {
                    int r = wm*32 + tm*16 + (lane >> 2);
                    int cb = kk*8 + (lane & 3);
                    af[t][tm][0] = A32[r*(AST/2) + cb];
                    af[t][tm][1] = A32[(r+8)*(AST/2) + cb];
                    af[t][tm][2] = A32[r*(AST/2) + cb + 4];
                    af[t][tm][3] = A32[(r+8)*(AST/2) + cb + 4];
                }
            }
            // B fragments
            uint32_t bfr[2][4][2];
            #pragma unroll
            for (int t = 0; t < 2; t++) {
                const unsigned short* B16 = (const unsigned short*)&Bs[t][0];
                #pragma unroll
                for (int tn = 0; tn < 4; tn++) {
                    int n = wn*32 + tn*8 + (lane >> 2);
                    int kb = kk*16 + (lane & 3)*2;
                    uint32_t l0 = B16[kb*BST + n],     h0 = B16[(kb+1)*BST + n];
                    uint32_t l1 = B16[(kb+8)*BST + n], h1 = B16[(kb+9)*BST + n];
                    bfr[t][tn][0] = l0 | (h0 << 16);
                    bfr[t][tn][1] = l1 | (h1 << 16);
                }
            }
            // 3 terms: Ah*Bh, Ah*Bl, Al*Bh
            #pragma unroll
            for (int tm = 0; tm < 2; tm++)
                #pragma unroll
                for (int tn = 0; tn < 4; tn++) {
                    mma_bf16(acc[tm][tn], af[0][tm], bfr[0][tn]);
                    mma_bf16(acc[tm][tn], af[0][tm], bfr[1][tn]);
                    mma_bf16(acc[tm][tn], af[1][tm], bfr[0][tn]);
                }
        }
        __syncthreads();
    }

    // epilogue: float2 direct stores
    #pragma unroll
    for (int tm = 0; tm < 2; tm++)
        #pragma unroll
        for (int tn = 0; tn < 4; tn++) {
            int r = m0 + wm*32 + tm*16 + (lane >> 2);
            int c = n0 + wn*32 + tn*8 + (lane & 3)*2;
            *(float2*)&Cp[(size_t)r*N + c]     = make_float2(acc[tm][tn][0], acc[tm][tn][1]);
            *(float2*)&Cp[(size_t)(r+8)*N + c] = make_float2(acc[tm][tn][2], acc[tm][tn][3]);
        }
}

// ---------------- q scan: per-pixel inv L2 norm + probe partials ----------------
__global__ void qscan_k(const float* __restrict__ q, float* __restrict__ qinv,
                        float* __restrict__ probe_part) {
    int bh = blockIdx.y;
    int px = blockIdx.x*256 + threadIdx.x;
    const float* base = q + (size_t)bh*DHEAD*NPIX + px;
    float s2 = 0.f;
    #pragma unroll 8
    for (int d = 0; d < DHEAD; d++) { float v = base[(size_t)d*NPIX]; s2 += v*v; }
    float inv = 1.f / fmaxf(sqrtf(s2), 1e-12f);
    qinv[(size_t)bh*NPIX + px] = inv;

    __shared__ float red2[DHEAD][8];
    int lane = threadIdx.x & 31, wid = threadIdx.x >> 5;
    for (int d = 0; d < DHEAD; d++) {
        float v = base[(size_t)d*NPIX] * inv;
        #pragma unroll
        for (int off = 16; off; off >>= 1) v += __shfl_xor_sync(0xffffffffu, v, off);
        if (lane == 0) red2[d][wid] = v;
    }
    __syncthreads();
    if (threadIdx.x < DHEAD) {
        float s = 0.f;
        #pragma unroll
        for (int w = 0; w < 8; w++) s += red2[threadIdx.x][w];
        probe_part[((size_t)bh*NQBLK + blockIdx.x)*DHEAD + threadIdx.x] = s;
    }
}

__global__ void probe_reduce_k(const float* __restrict__ part, float* __restrict__ probe) {
    int bh = blockIdx.x, d = threadIdx.x;
    float s = 0.f;
    for (int i = 0; i < NQBLK; i++) s += part[((size_t)bh*NQBLK + i)*DHEAD + d];
    probe[bh*DHEAD + d] = s;
}

// ---------------- k inv norm ----------------
__global__ void kinv_k(const float* __restrict__ k, float* __restrict__ kinv) {
    int bh = blockIdx.y;
    int px = blockIdx.x*256 + threadIdx.x;
    const float* base = k + (size_t)bh*DHEAD*CPIX + px;
    float s2 = 0.f;
    #pragma unroll 8
    for (int d = 0; d < DHEAD; d++) { float v = base[(size_t)d*CPIX]; s2 += v*v; }
    kinv[(size_t)bh*CPIX + px] = 1.f / fmaxf(sqrtf(s2), 1e-12f);
}

// ---------------- row/col |k| sums ----------------
__global__ void rowcol_k(const float* __restrict__ k, const float* __restrict__ kinv,
                         float* __restrict__ rowsum, float* __restrict__ colsum) {
    int d = blockIdx.x, bh = blockIdx.y, t = threadIdx.x; // 64 threads
    __shared__ float s[64*65];
    const float* base = k + ((size_t)bh*DHEAD + d)*CPIX;
    const float* inv  = kinv + (size_t)bh*CPIX;
    for (int h = 0; h < 64; h++) {
        int px = h*64 + t;
        s[h*65 + t] = fabsf(base[px]) * inv[px];
    }
    __syncthreads();
    float rs = 0.f, cs = 0.f;
    #pragma unroll 8
    for (int w = 0; w < 64; w++) rs += s[t*65 + w];
    #pragma unroll 8
    for (int h = 0; h < 64; h++) cs += s[h*65 + t];
    rowsum[((size_t)bh*DHEAD + d)*HC + t] = rs;
    colsum[((size_t)bh*DHEAD + d)*WC + t] = cs;
}

// ---------------- scores + exact top-8 (first index wins ties) ----------------
__global__ void topk_k(const float* __restrict__ probe, const float* __restrict__ rowsum,
                       const float* __restrict__ colsum, int* __restrict__ topidx) {
    int bh = blockIdx.x, t = threadIdx.x; // 64 threads
    __shared__ float sr[64], sc[64];
    __shared__ int th[8], tw[8];
    float r = 0.f, c = 0.f;
    for (int d = 0; d < DHEAD; d++) {
        float p = probe[bh*DHEAD + d];
        r += p * rowsum[((size_t)bh*DHEAD + d)*HC + t];
        c += p * colsum[((size_t)bh*DHEAD + d)*WC + t];
    }
    sr[t] = r; sc[t] = c;
    __syncthreads();
    if (t == 0) {
        bool used[64];
        for (int i = 0; i < 64; i++) used[i] = false;
        for (int i = 0; i < 8; i++) {
            float best = -1e38f; int bi = 0;
            for (int h = 0; h < 64; h++)
                if (!used[h] && sr[h] > best) { best = sr[h]; bi = h; }
            used[bi] = true; th[i] = bi;
        }
        for (int i = 0; i < 64; i++) used[i] = false;
        for (int i = 0; i < 8; i++) {
            float best = -1e38f; int bi = 0;
            for (int w = 0; w < 64; w++)
                if (!used[w] && sc[w] > best) { best = sc[w]; bi = w; }
            used[bi] = true; tw[i] = bi;
        }
        for (int i = 0; i < 8; i++)
            for (int j = 0; j < 8; j++)
                topidx[bh*NKV + i*8 + j] = th[i]*WC + tw[j];
    }
}

// ---------------- pack: gather+normalize k; compute v only at pruned positions ----------------
__global__ void pack_k(const float* __restrict__ k, const float* __restrict__ kinv,
                       const float* __restrict__ ctxn, const float* __restrict__ wkv,
                       const int* __restrict__ topidx,
                       float* __restrict__ kpack, float* __restrict__ vpack) {
    extern __shared__ float ctx_s[];   // [c][j] = ctx_s[c*64 + j]
    __shared__ int pos[NKV];
    int bh = blockIdx.x, b = bh >> 3, h = bh & 7;
    int tid = threadIdx.x;
    if (tid < NKV) pos[tid] = topidx[bh*NKV + tid];
    __syncthreads();

    int j = tid & 63, c0 = tid >> 6;
    for (int cc = 0; cc < 64; cc++) {
        int c = cc*4 + c0;
        ctx_s[c*64 + j] = ctxn[((size_t)b*CDIM + c)*CPIX + pos[j]];
    }

    #pragma unroll
    for (int i = 0; i < 16; i++) {
        int idx = tid + i*256;
        int jj = idx >> 6, d = idx & 63;
        int p = pos[jj];
        kpack[(size_t)bh*NKV*DHEAD + idx] =
            k[((size_t)bh*DHEAD + d)*CPIX + p] * kinv[(size_t)bh*CPIX + p];
    }
    __syncthreads();

    for (int dd = 0; dd < 16; dd++) {
        int d = dd*4 + c0;
        const float* wr = wkv + ((size_t)(INNER + h*DHEAD + d))*CDIM;
        float acc = 0.f;
        #pragma unroll 8
        for (int c = 0; c < CDIM; c++) acc += wr[c] * ctx_s[c*64 + j];
        vpack[(size_t)bh*NKV*DHEAD + j*DHEAD + d] = acc;
    }
}

// ---------------- fused attention: 128-query tile x 64 KV, writes bf16 hi/lo ----------------
#define ATTN_SMEM ((64*65 + 64*65 + 64*129 + 128*65) * 4)
__global__ void attn_k(const float* __restrict__ q, const float* __restrict__ qinv,
                       const float* __restrict__ kpack, const float* __restrict__ vpack,
                       __nv_bfloat16* __restrict__ oh, __nv_bfloat16* __restrict__ ol) {
    extern __shared__ float sm[];
    float* Ks = sm;                 // [j][d] pad 65
    float* Vs = Ks + 64*65;         // [j][d] pad 65
    float* Qs = Vs + 64*65;         // [d][p] pad 129 (reused as out_s)
    float* P  = Qs + 64*129;        // [p][j] pad 65

    int bh = blockIdx.y;
    int px0 = blockIdx.x * 128;
    int tid = threadIdx.x;
    int tx = tid & 15, ty = tid >> 4;

    for (int i = tid; i < NKV*DHEAD; i += 256) {
        int jj = i >> 6, d = i & 63;
        Ks[jj*65 + d] = kpack[(size_t)bh*NKV*DHEAD + i];
        Vs[jj*65 + d] = vpack[(size_t)bh*NKV*DHEAD + i];
    }
    const float* qb = q + (size_t)bh*DHEAD*NPIX + px0;
    const float* qi = qinv + (size_t)bh*NPIX + px0;
    for (int i = tid; i < 8192; i += 256) {
        int d = i >> 7, p = i & 127;
        Qs[d*129 + p] = qb[(size_t)d*NPIX + p] * qi[p];
    }
    __syncthreads();

    float acc[8][4];
    #pragma unroll
    for (int i = 0; i < 8; i++)
        #pragma unroll
        for (int jj = 0; jj < 4; jj++) acc[i][jj] = 0.f;
    for (int d = 0; d < DHEAD; d++) {
        float a[8], bv[4];
        #pragma unroll
        for (int i = 0; i < 8; i++)  a[i]  = Qs[d*129 + ty*8 + i];
        #pragma unroll
        for (int jj = 0; jj < 4; jj++) bv[jj] = Ks[(tx*4 + jj)*65 + d];
        #pragma unroll
        for (int i = 0; i < 8; i++)
            #pragma unroll
            for (int jj = 0; jj < 4; jj++) acc[i][jj] += a[i]*bv[jj];
    }
    #pragma unroll
    for (int i = 0; i < 8; i++)
        #pragma unroll
        for (int jj = 0; jj < 4; jj++)
            P[(ty*8 + i)*65 + tx*4 + jj] = acc[i][jj];
    __syncthreads();

    int lane = tid & 31, w = tid >> 5;
    for (int r = w; r < 128; r += 8) {
        float m = -1e30f;
        #pragma unroll
        for (int j = lane; j < 64; j += 32) m = fmaxf(m, P[r*65 + j]);
        #pragma unroll
        for (int off = 16; off; off >>= 1) m = fmaxf(m, __shfl_xor_sync(0xffffffffu, m, off));
        float s = 0.f;
        #pragma unroll
        for (int j = lane; j < 64; j += 32) { float e = expf(P[r*65 + j] - m); P[r*65 + j] = e; s += e; }
        #pragma unroll
        for (int off = 16; off; off >>= 1) s += __shfl_xor_sync(0xffffffffu, s, off);
        float invs = 1.f / s;
        #pragma unroll
        for (int j = lane; j < 64; j += 32) P[r*65 + j] *= invs;
    }
    __syncthreads();

    float acc2[8][4];
    #pragma unroll
    for (int i = 0; i < 8; i++)
        #pragma unroll
        for (int jj = 0; jj < 4; jj++) acc2[i][jj] = 0.f;
    for (int j = 0; j < NKV; j++) {
        float a[8], bv[4];
        #pragma unroll
        for (int i = 0; i < 8; i++)  a[i]  = P[(ty*8 + i)*65 + j];
        #pragma unroll
        for (int jj = 0; jj < 4; jj++) bv[jj] = Vs[j*65 + tx*4 + jj];
        #pragma unroll
        for (int i = 0; i < 8; i++)
            #pragma unroll
            for (int jj = 0; jj < 4; jj++) acc2[i][jj] += a[i]*bv[jj];
    }
    __syncthreads();
    #pragma unroll
    for (int i = 0; i < 8; i++)
        #pragma unroll
        for (int jj = 0; jj < 4; jj++)
            Qs[(tx*4 + jj)*129 + ty*8 + i] = acc2[i][jj];
    __syncthreads();
    size_t ob = (size_t)bh*DHEAD*NPIX + px0;
    for (int i = tid; i < 8192; i += 256) {
        int d = i >> 7, p = i & 127;
        float v = Qs[d*129 + p];
        __nv_bfloat16 h = __float2bfloat16(v);
        oh[ob + (size_t)d*NPIX + p] = h;
        ol[ob + (size_t)d*NPIX + p] = __float2bfloat16(v - __bfloat162float(h));
    }
}

// ---------------- final: channorm(obuf)*gamma + residual ----------------
__global__ void final_k(const float* __restrict__ x, const float* __restrict__ g,
                        const float* __restrict__ bb, const float* __restrict__ gamma,
                        const float* __restrict__ resid, float* __restrict__ y) {
    int px = blockIdx.x*256 + threadIdx.x;
    int b  = blockIdx.y;
    const float* xb = x + (size_t)b*CDIM*NPIX + px;
    float s = 0.f, s2 = 0.f;
    #pragma unroll 8
    for (int c = 0; c < CDIM; c++) { float v = xb[(size_t)c*NPIX]; s += v; s2 += v*v; }
    float mean = s * (1.f/CDIM);
    float var  = s2 * (1.f/CDIM) - mean*mean;
    float rstd = rsqrtf(var + EPS);
    float gm = gamma[0];
    const float* rb = resid + (size_t)b*CDIM*NPIX + px;
    float* yb = y + (size_t)b*CDIM*NPIX + px;
    #pragma unroll 8
    for (int c = 0; c < CDIM; c++)
        yb[(size_t)c*NPIX] = gm * ((xb[(size_t)c*NPIX] - mean)*rstd*g[c] + bb[c]) + rb[(size_t)c*NPIX];
}

// ---------------- launch ----------------
extern "C" void kernel_launch(void* const* d_in, const int* in_sizes, int n_in,
                              void* d_out, int out_size) {
    const float* query_source = (const float*)d_in[0];
    const float* context      = (const float*)d_in[1];
    const float* qs_g  = (const float*)d_in[2];
    const float* qs_b  = (const float*)d_in[3];
    const float* ctx_g = (const float*)d_in[4];
    const float* ctx_b = (const float*)d_in[5];
    const float* out_g = (const float*)d_in[6];
    const float* out_b = (const float*)d_in[7];
    const float* w_q   = (const float*)d_in[8];
    const float* w_kv  = (const float*)d_in[9];
    const float* w_out = (const float*)d_in[10];
    const float* gamma = (const float*)d_in[11];
    float* out = (float*)d_out;

    float *ctxn, *qb, *kb, *obuf, *qinv, *kinv, *ppart, *probe, *rowsum, *colsum,
          *kpack, *vpack;
    int* topidx;
    __nv_bfloat16 *ctxn_h, *ctxn_l, *qsn_h, *qsn_l, *att_h, *att_l,
                  *wq_h, *wq_l, *wk_h, *wk_l, *wo_h, *wo_l;
    cudaGetSymbolAddress((void**)&ctxn,  g_ctxn);
    cudaGetSymbolAddress((void**)&qb,    g_q);
    cudaGetSymbolAddress((void**)&kb,    g_k);
    cudaGetSymbolAddress((void**)&obuf,  g_obuf);
    cudaGetSymbolAddress((void**)&qinv,  g_qinv);
    cudaGetSymbolAddress((void**)&kinv,  g_kinv);
    cudaGetSymbolAddress((void**)&ppart, g_probe_part);
    cudaGetSymbolAddress((void**)&probe, g_probe);
    cudaGetSymbolAddress((void**)&rowsum,g_rowsum);
    cudaGetSymbolAddress((void**)&colsum,g_colsum);
    cudaGetSymbolAddress((void**)&topidx,g_topidx);
    cudaGetSymbolAddress((void**)&kpack, g_kpack);
    cudaGetSymbolAddress((void**)&vpack, g_vpack);
    cudaGetSymbolAddress((void**)&ctxn_h,g_ctxn_h);
    cudaGetSymbolAddress((void**)&ctxn_l,g_ctxn_l);
    cudaGetSymbolAddress((void**)&qsn_h, g_qsn_h);
    cudaGetSymbolAddress((void**)&qsn_l, g_qsn_l);
    cudaGetSymbolAddress((void**)&att_h, g_att_h);
    cudaGetSymbolAddress((void**)&att_l, g_att_l);
    cudaGetSymbolAddress((void**)&wq_h,  g_wq_h);
    cudaGetSymbolAddress((void**)&wq_l,  g_wq_l);
    cudaGetSymbolAddress((void**)&wk_h,  g_wk_h);
    cudaGetSymbolAddress((void**)&wk_l,  g_wk_l);
    cudaGetSymbolAddress((void**)&wo_h,  g_wout_h);
    cudaGetSymbolAddress((void**)&wo_l,  g_wout_l);

    cudaFuncSetAttribute(attn_k, cudaFuncAttributeMaxDynamicSharedMemorySize, ATTN_SMEM);
    cudaFuncSetAttribute(pack_k, cudaFuncAttributeMaxDynamicSharedMemorySize, 256*64*4);

    // 0) weight splits
    split_w_k<<<256, 256>>>(w_q,   wq_h, wq_l, INNER*CDIM);
    split_w_k<<<256, 256>>>(w_kv,  wk_h, wk_l, INNER*CDIM);   // first INNER rows = K weights
    split_w_k<<<256, 256>>>(w_out, wo_h, wo_l, CDIM*INNER);

    // 1) channel layernorms (ctx also keeps fp32 for V compute)
    channorm_split_k<<<dim3(CPIX/256, BATCH), 256>>>(context, ctx_g, ctx_b, ctxn, ctxn_h, ctxn_l, CPIX);
    channorm_split_k<<<dim3(NPIX/256, BATCH), 256>>>(query_source, qs_g, qs_b, nullptr, qsn_h, qsn_l, NPIX);

    // 2) projections via warp-MMA split-bf16 GEMM
    hmma_gemm_k<<<dim3(CPIX/64, INNER/128, BATCH), 256>>>(
        wk_h, wk_l, ctxn_h, ctxn_l, kb, INNER, CPIX, CDIM,
        (long)CDIM*CPIX, (long)INNER*CPIX);
    hmma_gemm_k<<<dim3(NPIX/64, INNER/128, BATCH), 256>>>(
        wq_h, wq_l, qsn_h, qsn_l, qb, INNER, NPIX, CDIM,
        (long)CDIM*NPIX, (long)INNER*NPIX);

    // 3) norms + probe + pruning scores
    qscan_k<<<dim3(NQBLK, BH), 256>>>(qb, qinv, ppart);
    probe_reduce_k<<<BH, DHEAD>>>(ppart, probe);
    kinv_k<<<dim3(CPIX/256, BH), 256>>>(kb, kinv);
    rowcol_k<<<dim3(DHEAD, BH), 64>>>(kb, kinv, rowsum, colsum);
    topk_k<<<BH, 64>>>(probe, rowsum, colsum, topidx);

    // 4) pack pruned K, compute pruned V
    pack_k<<<BH, 256, 256*64*4>>>(kb, kinv, ctxn, w_kv, topidx, kpack, vpack);

    // 5) fused attention (emits bf16 hi/lo for out-proj)
    attn_k<<<dim3(NPIX/128, BH), 256, ATTN_SMEM>>>(qb, qinv, kpack, vpack, att_h, att_l);

    // 6) output projection via warp-MMA
    hmma_gemm_k<<<dim3(NPIX/64, CDIM/128, BATCH), 256>>>(
        wo_h, wo_l, att_h, att_l, obuf, CDIM, NPIX, INNER,
        (long)INNER*NPIX, (long)CDIM*NPIX);

    // 7) final norm + gamma + residual
    final_k<<<dim3(NPIX/256, BATCH), 256>>>(obuf, out_g, out_b, gamma, query_source, out);
}

// round 4
// speedup vs baseline: 1.8958x; 1.1379x over previous
#include <cuda_runtime.h>
#include <cuda_bf16.h>
#include <math.h>
#include <stdint.h>

// ---------------- problem dims ----------------
#define BATCH   8
#define CDIM    256
#define INNER   512
#define NHEADS  8
#define DHEAD   64
#define HQ      96
#define WQ      96
#define NPIX    (HQ*WQ)     // 9216
#define HC      64
#define WC      64
#define CPIX    (HC*WC)     // 4096
#define BH      (BATCH*NHEADS) // 64
#define NKV     64          // 8x8 pruned
#define EPS     1e-5f
#define NQBLK   (NPIX/256)  // 36

// ---------------- scratch (static device memory; no allocs) ----------------
__device__ float  g_q    [BATCH*INNER*NPIX];   // q projection [bh][d][px]
__device__ float  g_k    [BATCH*INNER*CPIX];   // k projection [bh][d][px]
__device__ float  g_attno[BATCH*INNER*NPIX];   // attention out [bh][d][px]
__device__ float  g_obuf [BATCH*CDIM*NPIX];
__device__ float  g_qinv [BH*NPIX];
__device__ float  g_kinv [BH*CPIX];
__device__ float  g_probe_part[BH*NQBLK*DHEAD];
__device__ float  g_probe[BH*DHEAD];
__device__ float  g_rowsum[BH*DHEAD*HC];
__device__ float  g_colsum[BH*DHEAD*WC];
__device__ int    g_topidx[BH*NKV];
__device__ float2 g_ctx_stat[BATCH*CPIX];      // (mean, rstd) per ctx pixel
__device__ float2 g_qs_stat [BATCH*NPIX];      // (mean, rstd) per qs pixel
__device__ __nv_bfloat16 g_kh[BH*NKV*DHEAD], g_kl[BH*NKV*DHEAD];  // [j][d]
__device__ __nv_bfloat16 g_vh[BH*NKV*DHEAD], g_vl[BH*NKV*DHEAD];  // [d][j]

// ---------------- helpers ----------------
__device__ __forceinline__ unsigned short bf_bits(__nv_bfloat16 h) {
    return *reinterpret_cast<unsigned short*>(&h);
}
__device__ __forceinline__ void split1(float v, __nv_bfloat16& h, __nv_bfloat16& l) {
    h = __float2bfloat16(v);
    l = __float2bfloat16(v - __bfloat162float(h));
}
__device__ __forceinline__ void split2(float a, float b, uint32_t& hi, uint32_t& lo) {
    __nv_bfloat16 ha, la, hb, lb;
    split1(a, ha, la); split1(b, hb, lb);
    hi = (uint32_t)bf_bits(ha) | ((uint32_t)bf_bits(hb) << 16);
    lo = (uint32_t)bf_bits(la) | ((uint32_t)bf_bits(lb) << 16);
}
__device__ __forceinline__ void mma_bf16(float* c, const uint32_t* a, const uint32_t* b) {
    asm volatile(
        "mma.sync.aligned.m16n8k16.row.col.f32.bf16.bf16.f32 "
        "{%0,%1,%2,%3}, {%4,%5,%6,%7}, {%8,%9}, {%0,%1,%2,%3};\n"
        : "+f"(c[0]), "+f"(c[1]), "+f"(c[2]), "+f"(c[3])
        : "r"(a[0]), "r"(a[1]), "r"(a[2]), "r"(a[3]), "r"(b[0]), "r"(b[1]));
}

// ---------------- per-pixel layernorm stats ----------------
__global__ void stat_k(const float* __restrict__ x, float2* __restrict__ st, int HW) {
    int px = blockIdx.x*256 + threadIdx.x;
    int b  = blockIdx.y;
    const float* xb = x + (size_t)b*CDIM*HW + px;
    float s = 0.f, s2 = 0.f;
    #pragma unroll 8
    for (int c = 0; c < CDIM; c++) { float v = xb[(size_t)c*HW]; s += v; s2 += v*v; }
    float mean = s * (1.f/CDIM);
    float var  = s2 * (1.f/CDIM) - mean*mean;
    st[(size_t)b*HW + px] = make_float2(mean, rsqrtf(var + EPS));
}

// ---------------- HMMA split GEMM with fused layernorm on X ----------------
// C[b](M x N) = W(M x K) @ norm(X[b])(K x N); 3-term bf16 split, fp32 accum.
// 256 thr = 8 warps (4m x 2n); tile 128(M) x 64(N); K chunk 64.
// smem (dynamic): As hi/lo [128][74] bf16, Bs hi/lo [64][74] bf16 (B transposed [n][k])
#define GEMM_SMEM ((128*74*2 + 64*74*2) * 2)
__global__ void __launch_bounds__(256)
hmma_gemm_k(const float* __restrict__ W, const float* __restrict__ X,
            const float2* __restrict__ stat, const float* __restrict__ gvec,
            const float* __restrict__ bvec, float* __restrict__ C,
            int M, int N, int K, long strideX, long strideC) {
    extern __shared__ __nv_bfloat16 smbf[];
    __nv_bfloat16* As0 = smbf;             // hi [m][74]
    __nv_bfloat16* As1 = smbf + 9472;      // lo
    __nv_bfloat16* Bs0 = smbf + 18944;     // hi [n][74]
    __nv_bfloat16* Bs1 = smbf + 23680;     // lo

    int tid = threadIdx.x, lane = tid & 31, wid = tid >> 5;
    int wm = wid & 3, wn = wid >> 2;
    int n0 = blockIdx.x * 64, m0 = blockIdx.y * 128;
    const float* Xp = X + (size_t)blockIdx.z * strideX;
    float* Cp = C + (size_t)blockIdx.z * strideC;

    int ng = tid & 15;  // fixed n-group for B staging
    float2 st4[4];
    if (stat) {
        const float2* stp = stat + (size_t)blockIdx.z * N + n0 + ng*4;
        #pragma unroll
        for (int i = 0; i < 4; i++) st4[i] = stp[i];
    }

    float acc[2][4][4];
    #pragma unroll
    for (int i = 0; i < 2; i++)
        #pragma unroll
        for (int j = 0; j < 4; j++)
            #pragma unroll
            for (int l = 0; l < 4; l++) acc[i][j][l] = 0.f;

    int nch = K >> 6;
    for (int ch = 0; ch < nch; ch++) {
        int k0 = ch << 6;
        // stage A: raw fp32 weights, split on the fly (128m x 16 k-groups)
        #pragma unroll
        for (int p = 0; p < 8; p++) {
            int idx = tid + p*256;
            int m = idx >> 4, kg = idx & 15;
            float4 w = *(const float4*)&W[(size_t)(m0+m)*K + k0 + kg*4];
            uint32_t h01, l01, h23, l23;
            split2(w.x, w.y, h01, l01);
            split2(w.z, w.w, h23, l23);
            ((uint32_t*)As0)[m*37 + kg*2]     = h01;
            ((uint32_t*)As0)[m*37 + kg*2 + 1] = h23;
            ((uint32_t*)As1)[m*37 + kg*2]     = l01;
            ((uint32_t*)As1)[m*37 + kg*2 + 1] = l23;
        }
        // stage B: raw fp32 X, optional norm, split, transpose -> [n][k]
        #pragma unroll
        for (int p = 0; p < 4; p++) {
            int idx = tid + p*256;
            int k = idx >> 4;
            float4 xv = *(const float4*)&Xp[(size_t)(k0+k)*N + n0 + ng*4];
            if (stat) {
                float gg = gvec[k0+k], bb = bvec[k0+k];
                xv.x = (xv.x - st4[0].x)*st4[0].y*gg + bb;
                xv.y = (xv.y - st4[1].x)*st4[1].y*gg + bb;
                xv.z = (xv.z - st4[2].x)*st4[2].y*gg + bb;
                xv.w = (xv.w - st4[3].x)*st4[3].y*gg + bb;
            }
            float vv[4] = {xv.x, xv.y, xv.z, xv.w};
            #pragma unroll
            for (int e = 0; e < 4; e++) {
                __nv_bfloat16 h, l;
                split1(vv[e], h, l);
                Bs0[(ng*4+e)*74 + k] = h;
                Bs1[(ng*4+e)*74 + k] = l;
            }
        }
        __syncthreads();

        #pragma unroll
        for (int kk = 0; kk < 4; kk++) {
            uint32_t af[2][2][4], bfr[2][4][2];
            int cb = kk*8 + (lane & 3);
            #pragma unroll
            for (int t = 0; t < 2; t++) {
                const uint32_t* A32 = (const uint32_t*)(t ? As1 : As0);
                #pragma unroll
                for (int tm = 0; tm < 2; tm++) {
                    int r = wm*32 + tm*16 + (lane >> 2);
                    af[t][tm][0] = A32[r*37 + cb];
                    af[t][tm][1] = A32[(r+8)*37 + cb];
                    af[t][tm][2] = A32[r*37 + cb + 4];
                    af[t][tm][3] = A32[(r+8)*37 + cb + 4];
                }
                const uint32_t* B32 = (const uint32_t*)(t ? Bs1 : Bs0);
                #pragma unroll
                for (int tn = 0; tn < 4; tn++) {
                    int n = wn*32 + tn*8 + (lane >> 2);
                    bfr[t][tn][0] = B32[n*37 + cb];
                    bfr[t][tn][1] = B32[n*37 + cb + 4];
                }
            }
            #pragma unroll
            for (int tm = 0; tm < 2; tm++)
                #pragma unroll
                for (int tn = 0; tn < 4; tn++) {
                    mma_bf16(acc[tm][tn], af[0][tm], bfr[0][tn]);
                    mma_bf16(acc[tm][tn], af[0][tm], bfr[1][tn]);
                    mma_bf16(acc[tm][tn], af[1][tm], bfr[0][tn]);
                }
        }
        __syncthreads();
    }

    #pragma unroll
    for (int tm = 0; tm < 2; tm++)
        #pragma unroll
        for (int tn = 0; tn < 4; tn++) {
            int r = m0 + wm*32 + tm*16 + (lane >> 2);
            int c = n0 + wn*32 + tn*8 + (lane & 3)*2;
            *(float2*)&Cp[(size_t)r*N + c]     = make_float2(acc[tm][tn][0], acc[tm][tn][1]);
            *(float2*)&Cp[(size_t)(r+8)*N + c] = make_float2(acc[tm][tn][2], acc[tm][tn][3]);
        }
}

// ---------------- q scan: per-pixel inv L2 norm + probe partials ----------------
__global__ void qscan_k(const float* __restrict__ q, float* __restrict__ qinv,
                        float* __restrict__ probe_part) {
    int bh = blockIdx.y;
    int px = blockIdx.x*256 + threadIdx.x;
    const float* base = q + (size_t)bh*DHEAD*NPIX + px;
    float s2 = 0.f;
    #pragma unroll 8
    for (int d = 0; d < DHEAD; d++) { float v = base[(size_t)d*NPIX]; s2 += v*v; }
    float inv = 1.f / fmaxf(sqrtf(s2), 1e-12f);
    qinv[(size_t)bh*NPIX + px] = inv;

    __shared__ float red2[DHEAD][8];
    int lane = threadIdx.x & 31, wid = threadIdx.x >> 5;
    for (int d = 0; d < DHEAD; d++) {
        float v = base[(size_t)d*NPIX] * inv;
        #pragma unroll
        for (int off = 16; off; off >>= 1) v += __shfl_xor_sync(0xffffffffu, v, off);
        if (lane == 0) red2[d][wid] = v;
    }
    __syncthreads();
    if (threadIdx.x < DHEAD) {
        float s = 0.f;
        #pragma unroll
        for (int w = 0; w < 8; w++) s += red2[threadIdx.x][w];
        probe_part[((size_t)bh*NQBLK + blockIdx.x)*DHEAD + threadIdx.x] = s;
    }
}

__global__ void probe_reduce_k(const float* __restrict__ part, float* __restrict__ probe) {
    int bh = blockIdx.x, d = threadIdx.x;
    float s = 0.f;
    for (int i = 0; i < NQBLK; i++) s += part[((size_t)bh*NQBLK + i)*DHEAD + d];
    probe[bh*DHEAD + d] = s;
}

// ---------------- k inv norm ----------------
__global__ void kinv_k(const float* __restrict__ k, float* __restrict__ kinv) {
    int bh = blockIdx.y;
    int px = blockIdx.x*256 + threadIdx.x;
    const float* base = k + (size_t)bh*DHEAD*CPIX + px;
    float s2 = 0.f;
    #pragma unroll 8
    for (int d = 0; d < DHEAD; d++) { float v = base[(size_t)d*CPIX]; s2 += v*v; }
    kinv[(size_t)bh*CPIX + px] = 1.f / fmaxf(sqrtf(s2), 1e-12f);
}

// ---------------- row/col |k| sums ----------------
__global__ void rowcol_k(const float* __restrict__ k, const float* __restrict__ kinv,
                         float* __restrict__ rowsum, float* __restrict__ colsum) {
    int d = blockIdx.x, bh = blockIdx.y, t = threadIdx.x; // 64 threads
    __shared__ float s[64*65];
    const float* base = k + ((size_t)bh*DHEAD + d)*CPIX;
    const float* inv  = kinv + (size_t)bh*CPIX;
    for (int h = 0; h < 64; h++) {
        int px = h*64 + t;
        s[h*65 + t] = fabsf(base[px]) * inv[px];
    }
    __syncthreads();
    float rs = 0.f, cs = 0.f;
    #pragma unroll 8
    for (int w = 0; w < 64; w++) rs += s[t*65 + w];
    #pragma unroll 8
    for (int h = 0; h < 64; h++) cs += s[h*65 + t];
    rowsum[((size_t)bh*DHEAD + d)*HC + t] = rs;
    colsum[((size_t)bh*DHEAD + d)*WC + t] = cs;
}

// ---------------- scores + exact top-8 (first index wins ties) ----------------
__global__ void topk_k(const float* __restrict__ probe, const float* __restrict__ rowsum,
                       const float* __restrict__ colsum, int* __restrict__ topidx) {
    int bh = blockIdx.x, t = threadIdx.x; // 64 threads
    __shared__ float sr[64], sc[64];
    __shared__ int th[8], tw[8];
    float r = 0.f, c = 0.f;
    for (int d = 0; d < DHEAD; d++) {
        float p = probe[bh*DHEAD + d];
        r += p * rowsum[((size_t)bh*DHEAD + d)*HC + t];
        c += p * colsum[((size_t)bh*DHEAD + d)*WC + t];
    }
    sr[t] = r; sc[t] = c;
    __syncthreads();
    if (t == 0) {
        bool used[64];
        for (int i = 0; i < 64; i++) used[i] = false;
        for (int i = 0; i < 8; i++) {
            float best = -1e38f; int bi = 0;
            for (int h = 0; h < 64; h++)
                if (!used[h] && sr[h] > best) { best = sr[h]; bi = h; }
            used[bi] = true; th[i] = bi;
        }
        for (int i = 0; i < 64; i++) used[i] = false;
        for (int i = 0; i < 8; i++) {
            float best = -1e38f; int bi = 0;
            for (int w = 0; w < 64; w++)
                if (!used[w] && sc[w] > best) { best = sc[w]; bi = w; }
            used[bi] = true; tw[i] = bi;
        }
        for (int i = 0; i < 8; i++)
            for (int j = 0; j < 8; j++)
                topidx[bh*NKV + i*8 + j] = th[i]*WC + tw[j];
    }
}

// ---------------- pack: gather+normalize K (bf16 split [j][d]); V at pruned px (split [d][j]) ----------------
__global__ void pack_k(const float* __restrict__ k, const float* __restrict__ kinv,
                       const float* __restrict__ ctx_raw, const float2* __restrict__ cstat,
                       const float* __restrict__ cg, const float* __restrict__ cb_,
                       const float* __restrict__ wkv, const int* __restrict__ topidx,
                       __nv_bfloat16* __restrict__ kh, __nv_bfloat16* __restrict__ kl,
                       __nv_bfloat16* __restrict__ vh, __nv_bfloat16* __restrict__ vl) {
    extern __shared__ float ctx_s[];   // [c][j] = ctx_s[c*64 + j]
    __shared__ int pos[NKV];
    __shared__ float2 stj[NKV];
    int bh = blockIdx.x, b = bh >> 3, h = bh & 7;
    int tid = threadIdx.x;
    if (tid < NKV) {
        int p = topidx[bh*NKV + tid];
        pos[tid] = p;
        stj[tid] = cstat[(size_t)b*CPIX + p];
    }
    __syncthreads();

    int j = tid & 63, c0 = tid >> 6;
    float2 st = stj[j];
    for (int cc = 0; cc < 64; cc++) {
        int c = cc*4 + c0;
        float raw = ctx_raw[((size_t)b*CDIM + c)*CPIX + pos[j]];
        ctx_s[c*64 + j] = (raw - st.x)*st.y*cg[c] + cb_[c];
    }

    #pragma unroll
    for (int i = 0; i < 16; i++) {
        int idx = tid + i*256;
        int jj = idx >> 6, d = idx & 63;
        int p = pos[jj];
        float kv = k[((size_t)bh*DHEAD + d)*CPIX + p] * kinv[(size_t)bh*CPIX + p];
        __nv_bfloat16 hh, ll;
        split1(kv, hh, ll);
        kh[(size_t)bh*NKV*DHEAD + idx] = hh;   // [j][d]
        kl[(size_t)bh*NKV*DHEAD + idx] = ll;
    }
    __syncthreads();

    for (int dd = 0; dd < 16; dd++) {
        int d = dd*4 + c0;
        const float* wr = wkv + ((size_t)(INNER + h*DHEAD + d))*CDIM;
        float acc = 0.f;
        #pragma unroll 8
        for (int c = 0; c < CDIM; c++) acc += wr[c] * ctx_s[c*64 + j];
        __nv_bfloat16 hh, ll;
        split1(acc, hh, ll);
        vh[(size_t)bh*NKV*DHEAD + d*64 + j] = hh;  // [d][j]
        vl[(size_t)bh*NKV*DHEAD + d*64 + j] = ll;
    }
}

// ---------------- fused HMMA attention: 128-query tile x 64 KV ----------------
// smem: Qh/Ql [128][74] bf16 (reused as Ph/Pl), Kh/Kl [64][74] (reused as Vh/Vl),
//       P fp32 [128][68] (reused as Os [64][132])
#define ATTN_SMEM ((128*74*2 + 64*74*2)*2 + 128*68*4)
__global__ void __launch_bounds__(256)
attn_k(const float* __restrict__ qb_all, const float* __restrict__ qinv_all,
       const __nv_bfloat16* __restrict__ kh_all, const __nv_bfloat16* __restrict__ kl_all,
       const __nv_bfloat16* __restrict__ vh_all, const __nv_bfloat16* __restrict__ vl_all,
       float* __restrict__ attno) {
    extern __shared__ __nv_bfloat16 smbf[];
    __nv_bfloat16* Qh = smbf;                  // [px][74]  (later Ph/Pl)
    __nv_bfloat16* Ql = smbf + 9472;
    __nv_bfloat16* Kh = smbf + 18944;          // [j][74]   (later Vh/Vl as [d][74])
    __nv_bfloat16* Kl = smbf + 23680;
    float* P = (float*)(smbf + 28416);         // [128][68] (later Os [64][132])
    __shared__ float qiv[128];

    int bh = blockIdx.y;
    int px0 = blockIdx.x * 128;
    int tid = threadIdx.x, lane = tid & 31, wid = tid >> 5;
    int wm = wid & 3, wn = wid >> 2;

    const float* qb = qb_all + (size_t)bh*DHEAD*NPIX + px0;
    const float* qi = qinv_all + (size_t)bh*NPIX + px0;
    const uint32_t* khp = (const uint32_t*)(kh_all + (size_t)bh*NKV*DHEAD);
    const uint32_t* klp = (const uint32_t*)(kl_all + (size_t)bh*NKV*DHEAD);
    const uint32_t* vhp = (const uint32_t*)(vh_all + (size_t)bh*NKV*DHEAD);
    const uint32_t* vlp = (const uint32_t*)(vl_all + (size_t)bh*NKV*DHEAD);

    if (tid < 128) qiv[tid] = qi[tid];
    // stage K hi/lo: [j][d] -> [j][74], 32-bit copies
    for (int i = tid; i < 2048; i += 256) {
        int j = i >> 5, dp = i & 31;
        ((uint32_t*)Kh)[j*37 + dp] = khp[i];
        ((uint32_t*)Kl)[j*37 + dp] = klp[i];
    }
    __syncthreads();
    // stage Q: [d][px] global -> [px][74] smem, with qinv, split
    for (int i = tid; i < 8192; i += 256) {
        int d = i >> 7, p = i & 127;
        float v = qb[(size_t)d*NPIX + p] * qiv[p];
        __nv_bfloat16 hh, ll;
        split1(v, hh, ll);
        Qh[p*74 + d] = hh;
        Ql[p*74 + d] = ll;
    }
    __syncthreads();

    // QK^T: sim[px][j], 3-term split
    {
        float acc[2][4][4];
        #pragma unroll
        for (int i = 0; i < 2; i++)
            #pragma unroll
            for (int j = 0; j < 4; j++)
                #pragma unroll
                for (int l = 0; l < 4; l++) acc[i][j][l] = 0.f;
        #pragma unroll
        for (int kk = 0; kk < 4; kk++) {
            uint32_t af[2][2][4], bfr[2][4][2];
            int cb = kk*8 + (lane & 3);
            #pragma unroll
            for (int t = 0; t < 2; t++) {
                const uint32_t* A32 = (const uint32_t*)(t ? Ql : Qh);
                #pragma unroll
                for (int tm = 0; tm < 2; tm++) {
                    int r = wm*32 + tm*16 + (lane >> 2);
                    af[t][tm][0] = A32[r*37 + cb];
                    af[t][tm][1] = A32[(r+8)*37 + cb];
                    af[t][tm][2] = A32[r*37 + cb + 4];
                    af[t][tm][3] = A32[(r+8)*37 + cb + 4];
                }
                const uint32_t* B32 = (const uint32_t*)(t ? Kl : Kh);
                #pragma unroll
                for (int tn = 0; tn < 4; tn++) {
                    int n = wn*32 + tn*8 + (lane >> 2);
                    bfr[t][tn][0] = B32[n*37 + cb];
                    bfr[t][tn][1] = B32[n*37 + cb + 4];
                }
            }
            #pragma unroll
            for (int tm = 0; tm < 2; tm++)
                #pragma unroll
                for (int tn = 0; tn < 4; tn++) {
                    mma_bf16(acc[tm][tn], af[0][tm], bfr[0][tn]);
                    mma_bf16(acc[tm][tn], af[0][tm], bfr[1][tn]);
                    mma_bf16(acc[tm][tn], af[1][tm], bfr[0][tn]);
                }
        }
        #pragma unroll
        for (int tm = 0; tm < 2; tm++)
            #pragma unroll
            for (int tn = 0; tn < 4; tn++) {
                int r = wm*32 + tm*16 + (lane >> 2);
                int c = wn*32 + tn*8 + (lane & 3)*2;
                P[r*68 + c]       = acc[tm][tn][0];
                P[r*68 + c + 1]   = acc[tm][tn][1];
                P[(r+8)*68 + c]   = acc[tm][tn][2];
                P[(r+8)*68 + c+1] = acc[tm][tn][3];
            }
    }
    __syncthreads();

    // softmax rows (fp32)
    for (int r = wid; r < 128; r += 8) {
        float m = -1e30f;
        #pragma unroll
        for (int j = lane; j < 64; j += 32) m = fmaxf(m, P[r*68 + j]);
        #pragma unroll
        for (int off = 16; off; off >>= 1) m = fmaxf(m, __shfl_xor_sync(0xffffffffu, m, off));
        float s = 0.f;
        #pragma unroll
        for (int j = lane; j < 64; j += 32) { float e = expf(P[r*68 + j] - m); P[r*68 + j] = e; s += e; }
        #pragma unroll
        for (int off = 16; off; off >>= 1) s += __shfl_xor_sync(0xffffffffu, s, off);
        float invs = 1.f / s;
        #pragma unroll
        for (int j = lane; j < 64; j += 32) P[r*68 + j] *= invs;
    }
    __syncthreads();

    // split P into Qh/Ql region; stage V into Kh/Kl region ([d][74])
    for (int i = tid; i < 2048; i += 256) {
        int d = i >> 5, jp = i & 31;
        ((uint32_t*)Kh)[d*37 + jp] = vhp[i];
        ((uint32_t*)Kl)[d*37 + jp] = vlp[i];
    }
    for (int i = tid; i < 8192; i += 256) {
        int r = i >> 6, j = i & 63;
        float v = P[r*68 + j];
        __nv_bfloat16 hh, ll;
        split1(v, hh, ll);
        Qh[r*74 + j] = hh;
        Ql[r*74 + j] = ll;
    }
    __syncthreads();

    // P @ V: out[px][d], 3-term split
    {
        float acc[2][4][4];
        #pragma unroll
        for (int i = 0; i < 2; i++)
            #pragma unroll
            for (int j = 0; j < 4; j++)
                #pragma unroll
                for (int l = 0; l < 4; l++) acc[i][j][l] = 0.f;
        #pragma unroll
        for (int kk = 0; kk < 4; kk++) {
            uint32_t af[2][2][4], bfr[2][4][2];
            int cb = kk*8 + (lane & 3);
            #pragma unroll
            for (int t = 0; t < 2; t++) {
                const uint32_t* A32 = (const uint32_t*)(t ? Ql : Qh);
                #pragma unroll
                for (int tm = 0; tm < 2; tm++) {
                    int r = wm*32 + tm*16 + (lane >> 2);
                    af[t][tm][0] = A32[r*37 + cb];
                    af[t][tm][1] = A32[(r+8)*37 + cb];
                    af[t][tm][2] = A32[r*37 + cb + 4];
                    af[t][tm][3] = A32[(r+8)*37 + cb + 4];
                }
                const uint32_t* B32 = (const uint32_t*)(t ? Kl : Kh);
                #pragma unroll
                for (int tn = 0; tn < 4; tn++) {
                    int n = wn*32 + tn*8 + (lane >> 2);
                    bfr[t][tn][0] = B32[n*37 + cb];
                    bfr[t][tn][1] = B32[n*37 + cb + 4];
                }
            }
            #pragma unroll
            for (int tm = 0; tm < 2; tm++)
                #pragma unroll
                for (int tn = 0; tn < 4; tn++) {
                    mma_bf16(acc[tm][tn], af[0][tm], bfr[0][tn]);
                    mma_bf16(acc[tm][tn], af[0][tm], bfr[1][tn]);
                    mma_bf16(acc[tm][tn], af[1][tm], bfr[0][tn]);
                }
        }
        __syncthreads();   // all P-region reads (split loop) done; reuse as Os[64][132]
        float* Os = P;
        #pragma unroll
        for (int tm = 0; tm < 2; tm++)
            #pragma unroll
            for (int tn = 0; tn < 4; tn++) {
                int r = wm*32 + tm*16 + (lane >> 2);
                int c = wn*32 + tn*8 + (lane & 3)*2;
                Os[c*132 + r]       = acc[tm][tn][0];
                Os[(c+1)*132 + r]   = acc[tm][tn][1];
                Os[c*132 + r + 8]   = acc[tm][tn][2];
                Os[(c+1)*132 + r+8] = acc[tm][tn][3];
            }
    }
    __syncthreads();
    float* ob = attno + (size_t)bh*DHEAD*NPIX + px0;
    float* Os = P;
    for (int i = tid; i < 8192; i += 256) {
        int d = i >> 7, p = i & 127;
        ob[(size_t)d*NPIX + p] = Os[d*132 + p];
    }
}

// ---------------- final: channorm(obuf)*gamma + residual ----------------
__global__ void final_k(const float* __restrict__ x, const float* __restrict__ g,
                        const float* __restrict__ bb, const float* __restrict__ gamma,
                        const float* __restrict__ resid, float* __restrict__ y) {
    int px = blockIdx.x*256 + threadIdx.x;
    int b  = blockIdx.y;
    const float* xb = x + (size_t)b*CDIM*NPIX + px;
    float s = 0.f, s2 = 0.f;
    #pragma unroll 8
    for (int c = 0; c < CDIM; c++) { float v = xb[(size_t)c*NPIX]; s += v; s2 += v*v; }
    float mean = s * (1.f/CDIM);
    float var  = s2 * (1.f/CDIM) - mean*mean;
    float rstd = rsqrtf(var + EPS);
    float gm = gamma[0];
    const float* rb = resid + (size_t)b*CDIM*NPIX + px;
    float* yb = y + (size_t)b*CDIM*NPIX + px;
    #pragma unroll 8
    for (int c = 0; c < CDIM; c++)
        yb[(size_t)c*NPIX] = gm * ((xb[(size_t)c*NPIX] - mean)*rstd*g[c] + bb[c]) + rb[(size_t)c*NPIX];
}

// ---------------- launch ----------------
extern "C" void kernel_launch(void* const* d_in, const int* in_sizes, int n_in,
                              void* d_out, int out_size) {
    const float* query_source = (const float*)d_in[0];
    const float* context      = (const float*)d_in[1];
    const float* qs_g  = (const float*)d_in[2];
    const float* qs_b  = (const float*)d_in[3];
    const float* ctx_g = (const float*)d_in[4];
    const float* ctx_b = (const float*)d_in[5];
    const float* out_g = (const float*)d_in[6];
    const float* out_b = (const float*)d_in[7];
    const float* w_q   = (const float*)d_in[8];
    const float* w_kv  = (const float*)d_in[9];
    const float* w_out = (const float*)d_in[10];
    const float* gamma = (const float*)d_in[11];
    float* out = (float*)d_out;

    float *qb, *kb, *attno, *obuf, *qinv, *kinv, *ppart, *probe, *rowsum, *colsum;
    int* topidx;
    float2 *cstat, *qstat;
    __nv_bfloat16 *kh, *kl, *vh, *vl;
    cudaGetSymbolAddress((void**)&qb,    g_q);
    cudaGetSymbolAddress((void**)&kb,    g_k);
    cudaGetSymbolAddress((void**)&attno, g_attno);
    cudaGetSymbolAddress((void**)&obuf,  g_obuf);
    cudaGetSymbolAddress((void**)&qinv,  g_qinv);
    cudaGetSymbolAddress((void**)&kinv,  g_kinv);
    cudaGetSymbolAddress((void**)&ppart, g_probe_part);
    cudaGetSymbolAddress((void**)&probe, g_probe);
    cudaGetSymbolAddress((void**)&rowsum,g_rowsum);
    cudaGetSymbolAddress((void**)&colsum,g_colsum);
    cudaGetSymbolAddress((void**)&topidx,g_topidx);
    cudaGetSymbolAddress((void**)&cstat, g_ctx_stat);
    cudaGetSymbolAddress((void**)&qstat, g_qs_stat);
    cudaGetSymbolAddress((void**)&kh,    g_kh);
    cudaGetSymbolAddress((void**)&kl,    g_kl);
    cudaGetSymbolAddress((void**)&vh,    g_vh);
    cudaGetSymbolAddress((void**)&vl,    g_vl);

    cudaFuncSetAttribute(hmma_gemm_k, cudaFuncAttributeMaxDynamicSharedMemorySize, GEMM_SMEM);
    cudaFuncSetAttribute(attn_k, cudaFuncAttributeMaxDynamicSharedMemorySize, ATTN_SMEM);
    cudaFuncSetAttribute(pack_k, cudaFuncAttributeMaxDynamicSharedMemorySize, 256*64*4);

    // 1) per-pixel layernorm stats
    stat_k<<<dim3(CPIX/256, BATCH), 256>>>(context, cstat, CPIX);
    stat_k<<<dim3(NPIX/256, BATCH), 256>>>(query_source, qstat, NPIX);

    // 2) projections: fused norm + split inside GEMM
    hmma_gemm_k<<<dim3(CPIX/64, INNER/128, BATCH), 256, GEMM_SMEM>>>(
        w_kv, context, cstat, ctx_g, ctx_b, kb, INNER, CPIX, CDIM,
        (long)CDIM*CPIX, (long)INNER*CPIX);
    hmma_gemm_k<<<dim3(NPIX/64, INNER/128, BATCH), 256, GEMM_SMEM>>>(
        w_q, query_source, qstat, qs_g, qs_b, qb, INNER, NPIX, CDIM,
        (long)CDIM*NPIX, (long)INNER*NPIX);

    // 3) norms + probe + pruning scores
    qscan_k<<<dim3(NQBLK, BH), 256>>>(qb, qinv, ppart);
    probe_reduce_k<<<BH, DHEAD>>>(ppart, probe);
    kinv_k<<<dim3(CPIX/256, BH), 256>>>(kb, kinv);
    rowcol_k<<<dim3(DHEAD, BH), 64>>>(kb, kinv, rowsum, colsum);
    topk_k<<<BH, 64>>>(probe, rowsum, colsum, topidx);

    // 4) pack pruned K (split) + compute pruned V (split, transposed)
    pack_k<<<BH, 256, 256*64*4>>>(kb, kinv, context, cstat, ctx_g, ctx_b,
                                  w_kv, topidx, kh, kl, vh, vl);

    // 5) fused HMMA attention
    attn_k<<<dim3(NPIX/128, BH), 256, ATTN_SMEM>>>(qb, qinv, kh, kl, vh, vl, attno);

    // 6) output projection (no norm on X)
    hmma_gemm_k<<<dim3(NPIX/64, CDIM/128, BATCH), 256, GEMM_SMEM>>>(
        w_out, attno, nullptr, nullptr, nullptr, obuf, CDIM, NPIX, INNER,
        (long)INNER*NPIX, (long)CDIM*NPIX);

    // 7) final norm + gamma + residual
    final_k<<<dim3(NPIX/256, BATCH), 256>>>(obuf, out_g, out_b, gamma, query_source, out);
}

// round 5
// speedup vs baseline: 2.1701x; 1.1447x over previous
#include <cuda_runtime.h>
#include <cuda_bf16.h>
#include <math.h>
#include <stdint.h>

// ---------------- problem dims ----------------
#define BATCH   8
#define CDIM    256
#define INNER   512
#define NHEADS  8
#define DHEAD   64
#define HQ      96
#define WQ      96
#define NPIX    (HQ*WQ)     // 9216
#define HC      64
#define WC      64
#define CPIX    (HC*WC)     // 4096
#define BH      (BATCH*NHEADS) // 64
#define NKV     64          // 8x8 pruned
#define EPS     1e-5f
#define NQBLK   (NPIX/256)  // 36

// ---------------- scratch (static device memory; no allocs) ----------------
__device__ float  g_q    [BATCH*INNER*NPIX];   // q projection [bh][d][px]
__device__ float  g_k    [BATCH*INNER*CPIX];   // k projection [bh][d][px]
__device__ float  g_attno[BATCH*INNER*NPIX];   // attention out [bh][d][px]
__device__ float  g_obuf [BATCH*CDIM*NPIX];
__device__ float  g_qinv [BH*NPIX];
__device__ float  g_kinv [BH*CPIX];
__device__ float  g_probe_part[BH*NQBLK*DHEAD];
__device__ float  g_probe[BH*DHEAD];
__device__ float  g_rowsum[BH*DHEAD*HC];
__device__ float  g_colsum[BH*DHEAD*WC];
__device__ int    g_topidx[BH*NKV];
__device__ float2 g_ctx_stat[BATCH*CPIX];
__device__ float2 g_qs_stat [BATCH*NPIX];
__device__ __nv_bfloat16 g_kh[BH*NKV*DHEAD], g_kl[BH*NKV*DHEAD];  // [j][d]
__device__ __nv_bfloat16 g_vh[BH*NKV*DHEAD], g_vl[BH*NKV*DHEAD];  // [d][j]

// ---------------- helpers ----------------
__device__ __forceinline__ uint32_t smem_u32(const void* p) {
    uint32_t a;
    asm("{ .reg .u64 t; cvta.to.shared.u64 t, %1; cvt.u32.u64 %0, t; }" : "=r"(a) : "l"(p));
    return a;
}
__device__ __forceinline__ unsigned short bf_bits(__nv_bfloat16 h) {
    return *reinterpret_cast<unsigned short*>(&h);
}
__device__ __forceinline__ void split1(float v, __nv_bfloat16& h, __nv_bfloat16& l) {
    h = __float2bfloat16(v);
    l = __float2bfloat16(v - __bfloat162float(h));
}
__device__ __forceinline__ void split2(float a, float b, uint32_t& hi, uint32_t& lo) {
    __nv_bfloat16 ha, la, hb, lb;
    split1(a, ha, la); split1(b, hb, lb);
    hi = (uint32_t)bf_bits(ha) | ((uint32_t)bf_bits(hb) << 16);
    lo = (uint32_t)bf_bits(la) | ((uint32_t)bf_bits(lb) << 16);
}
__device__ __forceinline__ void mma_bf16(float* c, const uint32_t* a, const uint32_t* b) {
    asm volatile(
        "mma.sync.aligned.m16n8k16.row.col.f32.bf16.bf16.f32 "
        "{%0,%1,%2,%3}, {%4,%5,%6,%7}, {%8,%9}, {%0,%1,%2,%3};\n"
        : "+f"(c[0]), "+f"(c[1]), "+f"(c[2]), "+f"(c[3])
        : "r"(a[0]), "r"(a[1]), "r"(a[2]), "r"(a[3]), "r"(b[0]), "r"(b[1]));
}
__device__ __forceinline__ void ldsm_x4(uint32_t* r, uint32_t addr) {
    asm volatile("ldmatrix.sync.aligned.m8n8.x4.shared.b16 {%0,%1,%2,%3}, [%4];"
        : "=r"(r[0]), "=r"(r[1]), "=r"(r[2]), "=r"(r[3]) : "r"(addr));
}
__device__ __forceinline__ void ldsm_x4_t(uint32_t* r, uint32_t addr) {
    asm volatile("ldmatrix.sync.aligned.m8n8.x4.trans.shared.b16 {%0,%1,%2,%3}, [%4];"
        : "=r"(r[0]), "=r"(r[1]), "=r"(r[2]), "=r"(r[3]) : "r"(addr));
}

// row stride for bf16 tiles: 72 elems = 144 B (16B-aligned, conflict-free LDSM)
#define RS   72
#define RSB  144

// ---------------- per-pixel layernorm stats ----------------
__global__ void stat_k(const float* __restrict__ x, float2* __restrict__ st, int HW) {
    int px = blockIdx.x*256 + threadIdx.x;
    int b  = blockIdx.y;
    const float* xb = x + (size_t)b*CDIM*HW + px;
    float s = 0.f, s2 = 0.f;
    #pragma unroll 8
    for (int c = 0; c < CDIM; c++) { float v = xb[(size_t)c*HW]; s += v; s2 += v*v; }
    float mean = s * (1.f/CDIM);
    float var  = s2 * (1.f/CDIM) - mean*mean;
    st[(size_t)b*HW + px] = make_float2(mean, rsqrtf(var + EPS));
}

// ---------------- HMMA split GEMM (ldmatrix version) ----------------
// C[b](M x N) = W(M x K) @ norm(X[b])(K x N); 3-term bf16 split, fp32 accum.
// 256 thr = 8 warps (4m x 2n); tile 128(M) x 64(N); K chunk 64.
// smem: As hi/lo [128][RS] bf16 ([m][k]); Bs hi/lo [64][RS] ([k][n], read with .trans)
#define A_TERM 18432                      // 128*RSB
#define B_TERM 9216                       // 64*RSB
#define GEMM_SMEM (2*A_TERM + 2*B_TERM)   // 55296
__global__ void __launch_bounds__(256)
hmma_gemm_k(const float* __restrict__ W, const float* __restrict__ X,
            const float2* __restrict__ stat, const float* __restrict__ gvec,
            const float* __restrict__ bvec, float* __restrict__ C,
            int M, int N, int K, long strideX, long strideC) {
    extern __shared__ char smem[];
    char* As0 = smem;
    char* As1 = smem + A_TERM;
    char* Bs0 = smem + 2*A_TERM;
    char* Bs1 = smem + 2*A_TERM + B_TERM;
    uint32_t aBase = smem_u32(As0);
    uint32_t bBase = smem_u32(Bs0);

    int tid = threadIdx.x, lane = tid & 31, wid = tid >> 5;
    int wm = wid & 3, wn = wid >> 2;
    int n0 = blockIdx.x * 64, m0 = blockIdx.y * 128;
    const float* Xp = X + (size_t)blockIdx.z * strideX;
    float* Cp = C + (size_t)blockIdx.z * strideC;

    // ldmatrix lane offsets (bytes)
    // A (non-trans, [m][k]): tile = lane>>3; row += (tile&1)*8; col16 = tile>>1
    uint32_t aLane = (uint32_t)((wm*32 + ((lane>>3)&1)*8 + (lane&7))*RSB + (lane>>4)*16);
    // B (.trans, [k][n]): row k += (tile&1)*8 (kh); col octet = tile>>1
    uint32_t bLane = (uint32_t)((((lane>>3)&1)*8 + (lane&7))*RSB + (wn*32 + (lane>>4)*8)*2);

    // B staging: thread owns fixed 8-pixel group ng
    int ngf = tid & 7;
    float2 st8[8];
    if (stat) {
        const float2* stp = stat + (size_t)blockIdx.z * N + n0 + ngf*8;
        #pragma unroll
        for (int i = 0; i < 8; i++) st8[i] = stp[i];
    }

    float acc[2][4][4];
    #pragma unroll
    for (int i = 0; i < 2; i++)
        #pragma unroll
        for (int j = 0; j < 4; j++)
            #pragma unroll
            for (int l = 0; l < 4; l++) acc[i][j][l] = 0.f;

    int nch = K >> 6;
    for (int ch = 0; ch < nch; ch++) {
        int k0 = ch << 6;
        // stage A: 128 m x 8 kgroups(8 k each); 2x float4 load -> uint4 hi + uint4 lo
        #pragma unroll
        for (int p = 0; p < 4; p++) {
            int idx = tid + p*256;
            int m = idx >> 3, kg = idx & 7;
            const float* src = &W[(size_t)(m0+m)*K + k0 + kg*8];
            float4 w0 = *(const float4*)src;
            float4 w1 = *(const float4*)(src + 4);
            uint32_t h[4], l[4];
            split2(w0.x, w0.y, h[0], l[0]); split2(w0.z, w0.w, h[1], l[1]);
            split2(w1.x, w1.y, h[2], l[2]); split2(w1.z, w1.w, h[3], l[3]);
            *(uint4*)(As0 + m*RSB + kg*16) = make_uint4(h[0], h[1], h[2], h[3]);
            *(uint4*)(As1 + m*RSB + kg*16) = make_uint4(l[0], l[1], l[2], l[3]);
        }
        // stage B: 64 k x 8 ngroups(8 n each), natural [k][n] layout
        #pragma unroll
        for (int p = 0; p < 2; p++) {
            int idx = tid + p*256;
            int k = idx >> 3;
            const float* src = &Xp[(size_t)(k0+k)*N + n0 + ngf*8];
            float4 x0 = *(const float4*)src;
            float4 x1 = *(const float4*)(src + 4);
            if (stat) {
                float gg = gvec[k0+k], bb = bvec[k0+k];
                x0.x = (x0.x - st8[0].x)*st8[0].y*gg + bb;
                x0.y = (x0.y - st8[1].x)*st8[1].y*gg + bb;
                x0.z = (x0.z - st8[2].x)*st8[2].y*gg + bb;
                x0.w = (x0.w - st8[3].x)*st8[3].y*gg + bb;
                x1.x = (x1.x - st8[4].x)*st8[4].y*gg + bb;
                x1.y = (x1.y - st8[5].x)*st8[5].y*gg + bb;
                x1.z = (x1.z - st8[6].x)*st8[6].y*gg + bb;
                x1.w = (x1.w - st8[7].x)*st8[7].y*gg + bb;
            }
            uint32_t h[4], l[4];
            split2(x0.x, x0.y, h[0], l[0]); split2(x0.z, x0.w, h[1], l[1]);
            split2(x1.x, x1.y, h[2], l[2]); split2(x1.z, x1.w, h[3], l[3]);
            *(uint4*)(Bs0 + k*RSB + ngf*16) = make_uint4(h[0], h[1], h[2], h[3]);
            *(uint4*)(Bs1 + k*RSB + ngf*16) = make_uint4(l[0], l[1], l[2], l[3]);
        }
        __syncthreads();

        #pragma unroll
        for (int kk = 0; kk < 4; kk++) {
            uint32_t af[2][2][4], bfr[2][4][2];
            #pragma unroll
            for (int t = 0; t < 2; t++) {
                #pragma unroll
                for (int tm = 0; tm < 2; tm++)
                    ldsm_x4(af[t][tm], aBase + t*A_TERM + tm*16*RSB + kk*32 + aLane);
                #pragma unroll
                for (int pr = 0; pr < 2; pr++) {
                    uint32_t r[4];
                    ldsm_x4_t(r, bBase + t*B_TERM + kk*16*RSB + pr*32 + bLane);
                    bfr[t][pr*2][0]   = r[0]; bfr[t][pr*2][1]   = r[1];
                    bfr[t][pr*2+1][0] = r[2]; bfr[t][pr*2+1][1] = r[3];
                }
            }
            #pragma unroll
            for (int tm = 0; tm < 2; tm++)
                #pragma unroll
                for (int tn = 0; tn < 4; tn++) {
                    mma_bf16(acc[tm][tn], af[0][tm], bfr[0][tn]);
                    mma_bf16(acc[tm][tn], af[0][tm], bfr[1][tn]);
                    mma_bf16(acc[tm][tn], af[1][tm], bfr[0][tn]);
                }
        }
        __syncthreads();
    }

    #pragma unroll
    for (int tm = 0; tm < 2; tm++)
        #pragma unroll
        for (int tn = 0; tn < 4; tn++) {
            int r = m0 + wm*32 + tm*16 + (lane >> 2);
            int c = n0 + wn*32 + tn*8 + (lane & 3)*2;
            *(float2*)&Cp[(size_t)r*N + c]     = make_float2(acc[tm][tn][0], acc[tm][tn][1]);
            *(float2*)&Cp[(size_t)(r+8)*N + c] = make_float2(acc[tm][tn][2], acc[tm][tn][3]);
        }
}

// ---------------- q scan: per-pixel inv L2 norm + probe partials ----------------
__global__ void qscan_k(const float* __restrict__ q, float* __restrict__ qinv,
                        float* __restrict__ probe_part) {
    int bh = blockIdx.y;
    int px = blockIdx.x*256 + threadIdx.x;
    const float* base = q + (size_t)bh*DHEAD*NPIX + px;
    float s2 = 0.f;
    #pragma unroll 8
    for (int d = 0; d < DHEAD; d++) { float v = base[(size_t)d*NPIX]; s2 += v*v; }
    float inv = 1.f / fmaxf(sqrtf(s2), 1e-12f);
    qinv[(size_t)bh*NPIX + px] = inv;

    __shared__ float red2[DHEAD][8];
    int lane = threadIdx.x & 31, wid = threadIdx.x >> 5;
    for (int d = 0; d < DHEAD; d++) {
        float v = base[(size_t)d*NPIX] * inv;
        #pragma unroll
        for (int off = 16; off; off >>= 1) v += __shfl_xor_sync(0xffffffffu, v, off);
        if (lane == 0) red2[d][wid] = v;
    }
    __syncthreads();
    if (threadIdx.x < DHEAD) {
        float s = 0.f;
        #pragma unroll
        for (int w = 0; w < 8; w++) s += red2[threadIdx.x][w];
        probe_part[((size_t)bh*NQBLK + blockIdx.x)*DHEAD + threadIdx.x] = s;
    }
}

__global__ void probe_reduce_k(const float* __restrict__ part, float* __restrict__ probe) {
    int bh = blockIdx.x, d = threadIdx.x;
    float s = 0.f;
    for (int i = 0; i < NQBLK; i++) s += part[((size_t)bh*NQBLK + i)*DHEAD + d];
    probe[bh*DHEAD + d] = s;
}

// ---------------- k inv norm ----------------
__global__ void kinv_k(const float* __restrict__ k, float* __restrict__ kinv) {
    int bh = blockIdx.y;
    int px = blockIdx.x*256 + threadIdx.x;
    const float* base = k + (size_t)bh*DHEAD*CPIX + px;
    float s2 = 0.f;
    #pragma unroll 8
    for (int d = 0; d < DHEAD; d++) { float v = base[(size_t)d*CPIX]; s2 += v*v; }
    kinv[(size_t)bh*CPIX + px] = 1.f / fmaxf(sqrtf(s2), 1e-12f);
}

// ---------------- row/col |k| sums ----------------
__global__ void rowcol_k(const float* __restrict__ k, const float* __restrict__ kinv,
                         float* __restrict__ rowsum, float* __restrict__ colsum) {
    int d = blockIdx.x, bh = blockIdx.y, t = threadIdx.x; // 64 threads
    __shared__ float s[64*65];
    const float* base = k + ((size_t)bh*DHEAD + d)*CPIX;
    const float* inv  = kinv + (size_t)bh*CPIX;
    for (int h = 0; h < 64; h++) {
        int px = h*64 + t;
        s[h*65 + t] = fabsf(base[px]) * inv[px];
    }
    __syncthreads();
    float rs = 0.f, cs = 0.f;
    #pragma unroll 8
    for (int w = 0; w < 64; w++) rs += s[t*65 + w];
    #pragma unroll 8
    for (int h = 0; h < 64; h++) cs += s[h*65 + t];
    rowsum[((size_t)bh*DHEAD + d)*HC + t] = rs;
    colsum[((size_t)bh*DHEAD + d)*WC + t] = cs;
}

// ---------------- scores + exact top-8 (first index wins ties) ----------------
__global__ void topk_k(const float* __restrict__ probe, const float* __restrict__ rowsum,
                       const float* __restrict__ colsum, int* __restrict__ topidx) {
    int bh = blockIdx.x, t = threadIdx.x; // 64 threads
    __shared__ float sr[64], sc[64];
    __shared__ int th[8], tw[8];
    float r = 0.f, c = 0.f;
    for (int d = 0; d < DHEAD; d++) {
        float p = probe[bh*DHEAD + d];
        r += p * rowsum[((size_t)bh*DHEAD + d)*HC + t];
        c += p * colsum[((size_t)bh*DHEAD + d)*WC + t];
    }
    sr[t] = r; sc[t] = c;
    __syncthreads();
    if (t == 0) {
        bool used[64];
        for (int i = 0; i < 64; i++) used[i] = false;
        for (int i = 0; i < 8; i++) {
            float best = -1e38f; int bi = 0;
            for (int h = 0; h < 64; h++)
                if (!used[h] && sr[h] > best) { best = sr[h]; bi = h; }
            used[bi] = true; th[i] = bi;
        }
        for (int i = 0; i < 64; i++) used[i] = false;
        for (int i = 0; i < 8; i++) {
            float best = -1e38f; int bi = 0;
            for (int w = 0; w < 64; w++)
                if (!used[w] && sc[w] > best) { best = sc[w]; bi = w; }
            used[bi] = true; tw[i] = bi;
        }
        for (int i = 0; i < 8; i++)
            for (int j = 0; j < 8; j++)
                topidx[bh*NKV + i*8 + j] = th[i]*WC + tw[j];
    }
}

// ---------------- pack: K split [j][d]; V at pruned px split [d][j] ----------------
__global__ void pack_k(const float* __restrict__ k, const float* __restrict__ kinv,
                       const float* __restrict__ ctx_raw, const float2* __restrict__ cstat,
                       const float* __restrict__ cg, const float* __restrict__ cb_,
                       const float* __restrict__ wkv, const int* __restrict__ topidx,
                       __nv_bfloat16* __restrict__ kh, __nv_bfloat16* __restrict__ kl,
                       __nv_bfloat16* __restrict__ vh, __nv_bfloat16* __restrict__ vl) {
    extern __shared__ float ctx_s[];   // [c][j]
    __shared__ int pos[NKV];
    __shared__ float2 stj[NKV];
    int bh = blockIdx.x, b = bh >> 3, h = bh & 7;
    int tid = threadIdx.x;
    if (tid < NKV) {
        int p = topidx[bh*NKV + tid];
        pos[tid] = p;
        stj[tid] = cstat[(size_t)b*CPIX + p];
    }
    __syncthreads();

    int j = tid & 63, c0 = tid >> 6;
    float2 st = stj[j];
    for (int cc = 0; cc < 64; cc++) {
        int c = cc*4 + c0;
        float raw = ctx_raw[((size_t)b*CDIM + c)*CPIX + pos[j]];
        ctx_s[c*64 + j] = (raw - st.x)*st.y*cg[c] + cb_[c];
    }

    #pragma unroll
    for (int i = 0; i < 16; i++) {
        int idx = tid + i*256;
        int jj = idx >> 6, d = idx & 63;
        int p = pos[jj];
        float kv = k[((size_t)bh*DHEAD + d)*CPIX + p] * kinv[(size_t)bh*CPIX + p];
        __nv_bfloat16 hh, ll;
        split1(kv, hh, ll);
        kh[(size_t)bh*NKV*DHEAD + idx] = hh;
        kl[(size_t)bh*NKV*DHEAD + idx] = ll;
    }
    __syncthreads();

    for (int dd = 0; dd < 16; dd++) {
        int d = dd*4 + c0;
        const float* wr = wkv + ((size_t)(INNER + h*DHEAD + d))*CDIM;
        float acc = 0.f;
        #pragma unroll 8
        for (int c = 0; c < CDIM; c++) acc += wr[c] * ctx_s[c*64 + j];
        __nv_bfloat16 hh, ll;
        split1(acc, hh, ll);
        vh[(size_t)bh*NKV*DHEAD + d*64 + j] = hh;
        vl[(size_t)bh*NKV*DHEAD + d*64 + j] = ll;
    }
}

// ---------------- fused HMMA attention (ldmatrix) ----------------
// smem: Qh/Ql [128][RS] (later Ph/Pl), Kh/Kl [64][RS] (later Vh/Vl), P fp32 [128][68]
#define AQ_TERM 18432                     // 128*RSB
#define AK_TERM 9216                      // 64*RSB
#define ATTN_SMEM (2*AQ_TERM + 2*AK_TERM + 128*68*4)   // 90112
__global__ void __launch_bounds__(256)
attn_k(const float* __restrict__ qb_all, const float* __restrict__ qinv_all,
       const __nv_bfloat16* __restrict__ kh_all, const __nv_bfloat16* __restrict__ kl_all,
       const __nv_bfloat16* __restrict__ vh_all, const __nv_bfloat16* __restrict__ vl_all,
       float* __restrict__ attno) {
    extern __shared__ char smem[];
    char* Qh = smem;                        // [px][RS]
    char* Ql = smem + AQ_TERM;
    char* Kh = smem + 2*AQ_TERM;            // [j][RS] (later V [d][RS])
    char* Kl = smem + 2*AQ_TERM + AK_TERM;
    float* P = (float*)(smem + 2*AQ_TERM + 2*AK_TERM);  // [128][68]
    __shared__ float qiv[128];
    uint32_t qBase = smem_u32(Qh);
    uint32_t kBase = smem_u32(Kh);

    int bh = blockIdx.y;
    int px0 = blockIdx.x * 128;
    int tid = threadIdx.x, lane = tid & 31, wid = tid >> 5;
    int wm = wid & 3, wn = wid >> 2;

    const float* qb = qb_all + (size_t)bh*DHEAD*NPIX + px0;
    const float* qi = qinv_all + (size_t)bh*NPIX + px0;
    const uint32_t* khp = (const uint32_t*)(kh_all + (size_t)bh*NKV*DHEAD);
    const uint32_t* klp = (const uint32_t*)(kl_all + (size_t)bh*NKV*DHEAD);
    const uint32_t* vhp = (const uint32_t*)(vh_all + (size_t)bh*NKV*DHEAD);
    const uint32_t* vlp = (const uint32_t*)(vl_all + (size_t)bh*NKV*DHEAD);

    // ldmatrix lane offsets
    uint32_t aLane = (uint32_t)((wm*32 + ((lane>>3)&1)*8 + (lane&7))*RSB + (lane>>4)*16);
    // B non-trans from [n][k]: row n, col16 = kh
    uint32_t bLane = (uint32_t)(((lane>>4)*8 + (lane&7))*RSB + ((lane>>3)&1)*16 + wn*32*RSB);

    if (tid < 128) qiv[tid] = qi[tid];
    // stage K hi/lo: [j][d] 32-bit copies (warp spans d -> conflict-free)
    for (int i = tid; i < 2048; i += 256) {
        int j = i >> 5, dp = i & 31;
        ((uint32_t*)(Kh + j*RSB))[dp] = khp[i];
        ((uint32_t*)(Kl + j*RSB))[dp] = klp[i];
    }
    __syncthreads();
    // stage Q: transpose [d][px]->[px][RS] with qinv; lane decomposition 8p x 4dp
    #pragma unroll
    for (int it = 0; it < 16; it++) {
        int idx = tid + it*256;
        int p  = (idx & 7) | (((idx >> 5) & 15) << 3);
        int dp = ((idx >> 3) & 3) | ((idx >> 9) << 2);
        float iv = qiv[p];
        float v0 = qb[(size_t)(2*dp)*NPIX + p] * iv;
        float v1 = qb[(size_t)(2*dp+1)*NPIX + p] * iv;
        uint32_t hi, lo;
        split2(v0, v1, hi, lo);
        ((uint32_t*)(Qh + p*RSB))[dp] = hi;
        ((uint32_t*)(Ql + p*RSB))[dp] = lo;
    }
    __syncthreads();

    // QK^T -> P[px][j]
    {
        float acc[2][4][4];
        #pragma unroll
        for (int i = 0; i < 2; i++)
            #pragma unroll
            for (int j = 0; j < 4; j++)
                #pragma unroll
                for (int l = 0; l < 4; l++) acc[i][j][l] = 0.f;
        #pragma unroll
        for (int kk = 0; kk < 4; kk++) {
            uint32_t af[2][2][4], bfr[2][4][2];
            #pragma unroll
            for (int t = 0; t < 2; t++) {
                #pragma unroll
                for (int tm = 0; tm < 2; tm++)
                    ldsm_x4(af[t][tm], qBase + t*AQ_TERM + tm*16*RSB + kk*32 + aLane);
                #pragma unroll
                for (int pr = 0; pr < 2; pr++) {
                    uint32_t r[4];
                    ldsm_x4(r, kBase + t*AK_TERM + pr*16*RSB + kk*32 + bLane);
                    bfr[t][pr*2][0]   = r[0]; bfr[t][pr*2][1]   = r[1];
                    bfr[t][pr*2+1][0] = r[2]; bfr[t][pr*2+1][1] = r[3];
                }
            }
            #pragma unroll
            for (int tm = 0; tm < 2; tm++)
                #pragma unroll
                for (int tn = 0; tn < 4; tn++) {
                    mma_bf16(acc[tm][tn], af[0][tm], bfr[0][tn]);
                    mma_bf16(acc[tm][tn], af[0][tm], bfr[1][tn]);
                    mma_bf16(acc[tm][tn], af[1][tm], bfr[0][tn]);
                }
        }
        #pragma unroll
        for (int tm = 0; tm < 2; tm++)
            #pragma unroll
            for (int tn = 0; tn < 4; tn++) {
                int r = wm*32 + tm*16 + (lane >> 2);
                int c = wn*32 + tn*8 + (lane & 3)*2;
                P[r*68 + c]       = acc[tm][tn][0];
                P[r*68 + c + 1]   = acc[tm][tn][1];
                P[(r+8)*68 + c]   = acc[tm][tn][2];
                P[(r+8)*68 + c+1] = acc[tm][tn][3];
            }
    }
    __syncthreads();

    // softmax rows
    for (int r = wid; r < 128; r += 8) {
        float m = -1e30f;
        #pragma unroll
        for (int j = lane; j < 64; j += 32) m = fmaxf(m, P[r*68 + j]);
        #pragma unroll
        for (int off = 16; off; off >>= 1) m = fmaxf(m, __shfl_xor_sync(0xffffffffu, m, off));
        float s = 0.f;
        #pragma unroll
        for (int j = lane; j < 64; j += 32) { float e = expf(P[r*68 + j] - m); P[r*68 + j] = e; s += e; }
        #pragma unroll
        for (int off = 16; off; off >>= 1) s += __shfl_xor_sync(0xffffffffu, s, off);
        float invs = 1.f / s;
        #pragma unroll
        for (int j = lane; j < 64; j += 32) P[r*68 + j] *= invs;
    }
    __syncthreads();

    // stage V into K region ([d][RS], warp spans j -> conflict-free); split P into Q region
    for (int i = tid; i < 2048; i += 256) {
        int d = i >> 5, jp = i & 31;
        ((uint32_t*)(Kh + d*RSB))[jp] = vhp[i];
        ((uint32_t*)(Kl + d*RSB))[jp] = vlp[i];
    }
    #pragma unroll
    for (int it = 0; it < 16; it++) {
        int idx = tid + it*256;
        int r  = (idx & 7) | (((idx >> 5) & 15) << 3);
        int jp = ((idx >> 3) & 3) | ((idx >> 9) << 2);
        float v0 = P[r*68 + 2*jp];
        float v1 = P[r*68 + 2*jp + 1];
        uint32_t hi, lo;
        split2(v0, v1, hi, lo);
        ((uint32_t*)(Qh + r*RSB))[jp] = hi;
        ((uint32_t*)(Ql + r*RSB))[jp] = lo;
    }
    __syncthreads();

    // P @ V -> out[px][d]
    {
        float acc[2][4][4];
        #pragma unroll
        for (int i = 0; i < 2; i++)
            #pragma unroll
            for (int j = 0; j < 4; j++)
                #pragma unroll
                for (int l = 0; l < 4; l++) acc[i][j][l] = 0.f;
        #pragma unroll
        for (int kk = 0; kk < 4; kk++) {
            uint32_t af[2][2][4], bfr[2][4][2];
            #pragma unroll
            for (int t = 0; t < 2; t++) {
                #pragma unroll
                for (int tm = 0; tm < 2; tm++)
                    ldsm_x4(af[t][tm], qBase + t*AQ_TERM + tm*16*RSB + kk*32 + aLane);
                #pragma unroll
                for (int pr = 0; pr < 2; pr++) {
                    uint32_t r[4];
                    ldsm_x4(r, kBase + t*AK_TERM + pr*16*RSB + kk*32 + bLane);
                    bfr[t][pr*2][0]   = r[0]; bfr[t][pr*2][1]   = r[1];
                    bfr[t][pr*2+1][0] = r[2]; bfr[t][pr*2+1][1] = r[3];
                }
            }
            #pragma unroll
            for (int tm = 0; tm < 2; tm++)
                #pragma unroll
                for (int tn = 0; tn < 4; tn++) {
                    mma_bf16(acc[tm][tn], af[0][tm], bfr[0][tn]);
                    mma_bf16(acc[tm][tn], af[0][tm], bfr[1][tn]);
                    mma_bf16(acc[tm][tn], af[1][tm], bfr[0][tn]);
                }
        }
        __syncthreads();   // P reads done; reuse as Os[64][132]
        float* Os = P;
        #pragma unroll
        for (int tm = 0; tm < 2; tm++)
            #pragma unroll
            for (int tn = 0; tn < 4; tn++) {
                int r = wm*32 + tm*16 + (lane >> 2);
                int c = wn*32 + tn*8 + (lane & 3)*2;
                Os[c*132 + r]       = acc[tm][tn][0];
                Os[(c+1)*132 + r]   = acc[tm][tn][1];
                Os[c*132 + r + 8]   = acc[tm][tn][2];
                Os[(c+1)*132 + r+8] = acc[tm][tn][3];
            }
    }
    __syncthreads();
    float* ob = attno + (size_t)bh*DHEAD*NPIX + px0;
    float* Os = P;
    for (int i = tid; i < 8192; i += 256) {
        int d = i >> 7, p = i & 127;
        ob[(size_t)d*NPIX + p] = Os[d*132 + p];
    }
}

// ---------------- final: channorm(obuf)*gamma + residual ----------------
__global__ void final_k(const float* __restrict__ x, const float* __restrict__ g,
                        const float* __restrict__ bb, const float* __restrict__ gamma,
                        const float* __restrict__ resid, float* __restrict__ y) {
    int px = blockIdx.x*256 + threadIdx.x;
    int b  = blockIdx.y;
    const float* xb = x + (size_t)b*CDIM*NPIX + px;
    float s = 0.f, s2 = 0.f;
    #pragma unroll 8
    for (int c = 0; c < CDIM; c++) { float v = xb[(size_t)c*NPIX]; s += v; s2 += v*v; }
    float mean = s * (1.f/CDIM);
    float var  = s2 * (1.f/CDIM) - mean*mean;
    float rstd = rsqrtf(var + EPS);
    float gm = gamma[0];
    const float* rb = resid + (size_t)b*CDIM*NPIX + px;
    float* yb = y + (size_t)b*CDIM*NPIX + px;
    #pragma unroll 8
    for (int c = 0; c < CDIM; c++)
        yb[(size_t)c*NPIX] = gm * ((xb[(size_t)c*NPIX] - mean)*rstd*g[c] + bb[c]) + rb[(size_t)c*NPIX];
}

// ---------------- launch ----------------
extern "C" void kernel_launch(void* const* d_in, const int* in_sizes, int n_in,
                              void* d_out, int out_size) {
    const float* query_source = (const float*)d_in[0];
    const float* context      = (const float*)d_in[1];
    const float* qs_g  = (const float*)d_in[2];
    const float* qs_b  = (const float*)d_in[3];
    const float* ctx_g = (const float*)d_in[4];
    const float* ctx_b = (const float*)d_in[5];
    const float* out_g = (const float*)d_in[6];
    const float* out_b = (const float*)d_in[7];
    const float* w_q   = (const float*)d_in[8];
    const float* w_kv  = (const float*)d_in[9];
    const float* w_out = (const float*)d_in[10];
    const float* gamma = (const float*)d_in[11];
    float* out = (float*)d_out;

    float *qb, *kb, *attno, *obuf, *qinv, *kinv, *ppart, *probe, *rowsum, *colsum;
    int* topidx;
    float2 *cstat, *qstat;
    __nv_bfloat16 *kh, *kl, *vh, *vl;
    cudaGetSymbolAddress((void**)&qb,    g_q);
    cudaGetSymbolAddress((void**)&kb,    g_k);
    cudaGetSymbolAddress((void**)&attno, g_attno);
    cudaGetSymbolAddress((void**)&obuf,  g_obuf);
    cudaGetSymbolAddress((void**)&qinv,  g_qinv);
    cudaGetSymbolAddress((void**)&kinv,  g_kinv);
    cudaGetSymbolAddress((void**)&ppart, g_probe_part);
    cudaGetSymbolAddress((void**)&probe, g_probe);
    cudaGetSymbolAddress((void**)&rowsum,g_rowsum);
    cudaGetSymbolAddress((void**)&colsum,g_colsum);
    cudaGetSymbolAddress((void**)&topidx,g_topidx);
    cudaGetSymbolAddress((void**)&cstat, g_ctx_stat);
    cudaGetSymbolAddress((void**)&qstat, g_qs_stat);
    cudaGetSymbolAddress((void**)&kh,    g_kh);
    cudaGetSymbolAddress((void**)&kl,    g_kl);
    cudaGetSymbolAddress((void**)&vh,    g_vh);
    cudaGetSymbolAddress((void**)&vl,    g_vl);

    cudaFuncSetAttribute(hmma_gemm_k, cudaFuncAttributeMaxDynamicSharedMemorySize, GEMM_SMEM);
    cudaFuncSetAttribute(attn_k, cudaFuncAttributeMaxDynamicSharedMemorySize, ATTN_SMEM);
    cudaFuncSetAttribute(pack_k, cudaFuncAttributeMaxDynamicSharedMemorySize, 256*64*4);

    // 1) per-pixel layernorm stats
    stat_k<<<dim3(CPIX/256, BATCH), 256>>>(context, cstat, CPIX);
    stat_k<<<dim3(NPIX/256, BATCH), 256>>>(query_source, qstat, NPIX);

    // 2) projections: fused norm + split inside GEMM
    hmma_gemm_k<<<dim3(CPIX/64, INNER/128, BATCH), 256, GEMM_SMEM>>>(
        w_kv, context, cstat, ctx_g, ctx_b, kb, INNER, CPIX, CDIM,
        (long)CDIM*CPIX, (long)INNER*CPIX);
    hmma_gemm_k<<<dim3(NPIX/64, INNER/128, BATCH), 256, GEMM_SMEM>>>(
        w_q, query_source, qstat, qs_g, qs_b, qb, INNER, NPIX, CDIM,
        (long)CDIM*NPIX, (long)INNER*NPIX);

    // 3) norms + probe + pruning scores
    qscan_k<<<dim3(NQBLK, BH), 256>>>(qb, qinv, ppart);
    probe_reduce_k<<<BH, DHEAD>>>(ppart, probe);
    kinv_k<<<dim3(CPIX/256, BH), 256>>>(kb, kinv);
    rowcol_k<<<dim3(DHEAD, BH), 64>>>(kb, kinv, rowsum, colsum);
    topk_k<<<BH, 64>>>(probe, rowsum, colsum, topidx);

    // 4) pack pruned K (split) + compute pruned V (split, transposed)
    pack_k<<<BH, 256, 256*64*4>>>(kb, kinv, context, cstat, ctx_g, ctx_b,
                                  w_kv, topidx, kh, kl, vh, vl);

    // 5) fused HMMA attention
    attn_k<<<dim3(NPIX/128, BH), 256, ATTN_SMEM>>>(qb, qinv, kh, kl, vh, vl, attno);

    // 6) output projection
    hmma_gemm_k<<<dim3(NPIX/64, CDIM/128, BATCH), 256, GEMM_SMEM>>>(
        w_out, attno, nullptr, nullptr, nullptr, obuf, CDIM, NPIX, INNER,
        (long)INNER*NPIX, (long)CDIM*NPIX);

    // 7) final norm + gamma + residual
    final_k<<<dim3(NPIX/256, BATCH), 256>>>(obuf, out_g, out_b, gamma, query_source, out);
}